// round 11
// baseline (speedup 1.0000x reference)
#include <cuda_runtime.h>
#include <cuda_bf16.h>
#include <cstdint>

#define S_LEN 2048
#define DMODEL 1024
#define NHEAD 16
#define HSZ 64
#define N3 (3 * DMODEL)

typedef __nv_bfloat16 bf16;

// ---------------- scratch (__device__ globals; no allocations) -------------
__device__ bf16 g_ah[S_LEN * DMODEL];        // hidden hi
__device__ bf16 g_al[S_LEN * DMODEL];        // hidden lo
__device__ bf16 g_wth[N3 * DMODEL];          // W_attn^T hi [3072,1024]
__device__ bf16 g_wtl[N3 * DMODEL];          // W_attn^T lo
__device__ bf16 g_pth[DMODEL * DMODEL];      // W_proj^T hi
__device__ bf16 g_ptl[DMODEL * DMODEL];      // W_proj^T lo
__device__ bf16 g_qkvh[S_LEN * N3];          // QKV hi (GEMM epilogue split)
__device__ bf16 g_qkvl[S_LEN * N3];          // QKV lo
__device__ bf16 g_oh[S_LEN * DMODEL];        // attn out hi
__device__ bf16 g_ol[S_LEN * DMODEL];        // attn out lo

// ---------------- PTX helpers (compute_103-safe, no 'a' features) ----------
__device__ __forceinline__ uint32_t smem_u32(const void* p) {
    uint32_t a;
    asm("{ .reg .u64 t; cvta.to.shared.u64 t, %1; cvt.u32.u64 %0, t; }"
        : "=r"(a) : "l"(p));
    return a;
}
__device__ __forceinline__ void cp16(uint32_t dst, const void* src) {
    asm volatile("cp.async.cg.shared.global [%0], [%1], 16;"
                 :: "r"(dst), "l"(src) : "memory");
}
__device__ __forceinline__ void cp_commit() {
    asm volatile("cp.async.commit_group;" ::: "memory");
}
__device__ __forceinline__ void ldsm_x4(uint32_t* r, uint32_t a) {
    asm volatile("ldmatrix.sync.aligned.m8n8.x4.shared.b16 {%0,%1,%2,%3}, [%4];"
                 : "=r"(r[0]), "=r"(r[1]), "=r"(r[2]), "=r"(r[3]) : "r"(a));
}
__device__ __forceinline__ void ldsm_x4t(uint32_t* r, uint32_t a) {
    asm volatile("ldmatrix.sync.aligned.m8n8.x4.trans.shared.b16 {%0,%1,%2,%3}, [%4];"
                 : "=r"(r[0]), "=r"(r[1]), "=r"(r[2]), "=r"(r[3]) : "r"(a));
}
__device__ __forceinline__ void mma16816(float* c, const uint32_t* a,
                                         const uint32_t* b) {
    asm volatile(
        "mma.sync.aligned.m16n8k16.row.col.f32.bf16.bf16.f32 "
        "{%0,%1,%2,%3}, {%4,%5,%6,%7}, {%8,%9}, {%0,%1,%2,%3};"
        : "+f"(c[0]), "+f"(c[1]), "+f"(c[2]), "+f"(c[3])
        : "r"(a[0]), "r"(a[1]), "r"(a[2]), "r"(a[3]), "r"(b[0]), "r"(b[1]));
}
// fma-pipe exp(x); rel err ~2e-6
__device__ __forceinline__ float fexp(float x) {
    float y = fmaxf(x * 1.4426950408889634f, -126.f);
    float z = y + 12582912.f;
    int i = __float_as_int(z) - 0x4B400000;
    float f = y - (z - 12582912.f);
    float p = 1.3333558146e-3f;
    p = fmaf(p, f, 9.6181291794e-3f);
    p = fmaf(p, f, 5.5504108665e-2f);
    p = fmaf(p, f, 2.4022650696e-1f);
    p = fmaf(p, f, 6.9314718056e-1f);
    p = fmaf(p, f, 1.0f);
    return __int_as_float(__float_as_int(p) + (i << 23));
}
__device__ __forceinline__ uint32_t pack_bf16(float x, float y) {
    __nv_bfloat162 t = __floats2bfloat162_rn(x, y);
    return *(uint32_t*)&t;
}

// ---------------------------------------------------------------------------
__global__ void split_kernel(const float* __restrict__ x,
                             bf16* __restrict__ hi, bf16* __restrict__ lo) {
    const int i = blockIdx.x * blockDim.x + threadIdx.x;
    float4 v = ((const float4*)x)[i];
    bf16 h0 = __float2bfloat16(v.x), h1 = __float2bfloat16(v.y);
    bf16 h2 = __float2bfloat16(v.z), h3 = __float2bfloat16(v.w);
    union { __nv_bfloat162 b[2]; uint2 u; } H, L;
    H.b[0] = __nv_bfloat162(h0, h1);
    H.b[1] = __nv_bfloat162(h2, h3);
    L.b[0] = __nv_bfloat162(__float2bfloat16(v.x - __bfloat162float(h0)),
                            __float2bfloat16(v.y - __bfloat162float(h1)));
    L.b[1] = __nv_bfloat162(__float2bfloat16(v.z - __bfloat162float(h2)),
                            __float2bfloat16(v.w - __bfloat162float(h3)));
    ((uint2*)hi)[i] = H.u;
    ((uint2*)lo)[i] = L.u;
}

__global__ void transpose_split(const float* __restrict__ W,
                                bf16* __restrict__ Th, bf16* __restrict__ Tl,
                                int K, int N) {
    __shared__ float tile[32][33];
    const int n0 = blockIdx.x * 32, k0 = blockIdx.y * 32;
    const int tx = threadIdx.x, ty = threadIdx.y;
#pragma unroll
    for (int i = 0; i < 4; i++)
        tile[ty + 8 * i][tx] = W[(size_t)(k0 + ty + 8 * i) * N + n0 + tx];
    __syncthreads();
#pragma unroll
    for (int i = 0; i < 4; i++) {
        const float x = tile[tx][ty + 8 * i];
        const bf16 h = __float2bfloat16(x);
        const size_t o = (size_t)(n0 + ty + 8 * i) * K + k0 + tx;
        Th[o] = h;
        Tl[o] = __float2bfloat16(x - __bfloat162float(h));
    }
}

// ---------------------------------------------------------------------------
// HMMA GEMM: C = Ah*Bh^T + Ah*Bl^T + Al*Bh^T + bias
// CTA 128x128, BK=32, 8 warps (2x4), warp tile 64x32, cp.async 2-stage.
// 2 CTAs/SM (reg target 128); B frags via ldsm_x4 over nt-pairs.
// ---------------------------------------------------------------------------
template <int NDIM, int KDIM, bool SPLIT>
__global__ __launch_bounds__(256, 2)
void gemm_hmma(const bf16* __restrict__ Ah_, const bf16* __restrict__ Al_,
               const bf16* __restrict__ Bh_, const bf16* __restrict__ Bl_,
               const float* __restrict__ bias, float* __restrict__ C,
               bf16* __restrict__ Ch, bf16* __restrict__ Cl) {
    extern __shared__ __align__(128) char smem[];
    constexpr int TILE = 128 * 80;
    constexpr int STAGE = 4 * TILE;
    const int tid = threadIdx.x, lane = tid & 31, wid = tid >> 5;
    const int warp_m = wid & 1, warp_n = wid >> 1;
    const int bx = blockIdx.x, by = blockIdx.y;
    const uint32_t sb = smem_u32(smem);

    const bf16* gsrc[4] = {Ah_ + (size_t)(by * 128) * KDIM,
                           Al_ + (size_t)(by * 128) * KDIM,
                           Bh_ + (size_t)(bx * 128) * KDIM,
                           Bl_ + (size_t)(bx * 128) * KDIM};

    auto issue = [&](int t) {
        const uint32_t stb = sb + (uint32_t)((t & 1) * STAGE);
        const int k0 = t * 32;
#pragma unroll
        for (int tl = 0; tl < 4; tl++) {
#pragma unroll
            for (int i = 0; i < 2; i++) {
                const int c = tid + i * 256;
                const int row = c >> 2, cc = c & 3;
                cp16(stb + (uint32_t)(tl * TILE + row * 80 + cc * 16),
                     gsrc[tl] + (size_t)row * KDIM + k0 + cc * 8);
            }
        }
        cp_commit();
    };

    float c[4][4][4];
#pragma unroll
    for (int m = 0; m < 4; m++)
#pragma unroll
        for (int n = 0; n < 4; n++)
#pragma unroll
            for (int k = 0; k < 4; k++) c[m][n][k] = 0.f;

    issue(0);
    constexpr int NT = KDIM / 32;
    for (int t = 0; t < NT; t++) {
        if (t + 1 < NT) {
            issue(t + 1);
            asm volatile("cp.async.wait_group 1;" ::: "memory");
        } else {
            asm volatile("cp.async.wait_group 0;" ::: "memory");
        }
        __syncthreads();
        const uint32_t base = sb + (uint32_t)((t & 1) * STAGE);
#pragma unroll
        for (int ks = 0; ks < 2; ks++) {
            uint32_t ah[4][4], al[4][4], bh4[2][4], bl4[2][4];
#pragma unroll
            for (int mt = 0; mt < 4; mt++) {
                const int row = warp_m * 64 + mt * 16 + (lane & 15);
                const uint32_t off =
                    (uint32_t)(row * 80 + ks * 32 + (lane >> 4) * 16);
                ldsm_x4(ah[mt], base + 0 * TILE + off);
                ldsm_x4(al[mt], base + 1 * TILE + off);
            }
#pragma unroll
            for (int np = 0; np < 2; np++) {
                const int rowb = warp_n * 32 + np * 16 + (lane & 15);
                const uint32_t offb =
                    (uint32_t)(rowb * 80 + ks * 32 + (lane >> 4) * 16);
                ldsm_x4(bh4[np], base + 2 * TILE + offb);
                ldsm_x4(bl4[np], base + 3 * TILE + offb);
            }
#pragma unroll
            for (int mt = 0; mt < 4; mt++)
#pragma unroll
                for (int nt = 0; nt < 4; nt++) {
                    const int np = nt >> 1, od = nt & 1;
                    uint32_t bh[2] = {bh4[np][od], bh4[np][od + 2]};
                    uint32_t bl[2] = {bl4[np][od], bl4[np][od + 2]};
                    mma16816(c[mt][nt], ah[mt], bh);
                    mma16816(c[mt][nt], ah[mt], bl);
                    mma16816(c[mt][nt], al[mt], bh);
                }
        }
        __syncthreads();
    }

#pragma unroll
    for (int mt = 0; mt < 4; mt++) {
        const int row0 = by * 128 + warp_m * 64 + mt * 16 + (lane >> 2);
#pragma unroll
        for (int nt = 0; nt < 4; nt++) {
            const int col = bx * 128 + warp_n * 32 + nt * 8 + (lane & 3) * 2;
            const float b0 = bias[col], b1 = bias[col + 1];
            const float v00 = c[mt][nt][0] + b0, v01 = c[mt][nt][1] + b1;
            const float v10 = c[mt][nt][2] + b0, v11 = c[mt][nt][3] + b1;
            if (SPLIT) {
                const bf16 h00 = __float2bfloat16(v00), h01 = __float2bfloat16(v01);
                const bf16 h10 = __float2bfloat16(v10), h11 = __float2bfloat16(v11);
                const size_t o0 = (size_t)row0 * NDIM + col;
                const size_t o1 = (size_t)(row0 + 8) * NDIM + col;
                *(__nv_bfloat162*)&Ch[o0] = __nv_bfloat162(h00, h01);
                *(__nv_bfloat162*)&Ch[o1] = __nv_bfloat162(h10, h11);
                *(__nv_bfloat162*)&Cl[o0] = __nv_bfloat162(
                    __float2bfloat16(v00 - __bfloat162float(h00)),
                    __float2bfloat16(v01 - __bfloat162float(h01)));
                *(__nv_bfloat162*)&Cl[o1] = __nv_bfloat162(
                    __float2bfloat16(v10 - __bfloat162float(h10)),
                    __float2bfloat16(v11 - __bfloat162float(h11)));
            } else {
                *(float2*)&C[(size_t)row0 * NDIM + col] = make_float2(v00, v01);
                *(float2*)&C[(size_t)(row0 + 8) * NDIM + col] = make_float2(v10, v11);
            }
        }
    }
}

// ---------------------------------------------------------------------------
// FlashAttention-2 causal, HMMA 3-term bf16. 1 head x 128 rows per CTA,
// 8 warps x m16, 64-key tiles, 2 CTAs/SM target, x4 ldmatrix pairs.
// ---------------------------------------------------------------------------
__global__ __launch_bounds__(256, 2)
void attn_flash() {
    extern __shared__ __align__(128) char smem[];
    constexpr int RS = 144;
    constexpr int QH_OFF = 0, QL_OFF = 128 * RS;
    constexpr int KV_OFF = 2 * 128 * RS;
    constexpr int ARR = 64 * RS;
    constexpr int KV_STG = 4 * ARR;

    const int tid = threadIdx.x, lane = tid & 31, wid = tid >> 5;
    const int hd = blockIdx.y;
    const int bx = gridDim.x - 1 - blockIdx.x;   // heavy first
    const uint32_t sb = smem_u32(smem);
    const int rbase = bx * 128 + wid * 16;
    const float scale = rsqrtf((float)S_LEN);    // ref scales by sqrt(S)

    {
        const size_t qg = (size_t)(bx * 128) * N3 + hd * HSZ;
#pragma unroll
        for (int i = 0; i < 4; i++) {
            const int idx = tid + i * 256;
            const int row = idx >> 3, ch = idx & 7;
            const size_t g = qg + (size_t)row * N3 + ch * 8;
            cp16(sb + QH_OFF + (uint32_t)(row * RS + ch * 16), g_qkvh + g);
            cp16(sb + QL_OFF + (uint32_t)(row * RS + ch * 16), g_qkvl + g);
        }
    }

    auto issueKV = [&](int t) {
        const int stg = t & 1;
        const int j0 = t * 64;
        const uint32_t kb = sb + KV_OFF + (uint32_t)(stg * KV_STG);
#pragma unroll
        for (int i = 0; i < 2; i++) {
            const int idx = tid + i * 256;
            const int row = idx >> 3, ch = idx & 7;
            const uint32_t so = (uint32_t)(row * RS + ch * 16);
            const size_t gk = (size_t)(j0 + row) * N3 + DMODEL + hd * HSZ + ch * 8;
            const size_t gv = (size_t)(j0 + row) * N3 + 2 * DMODEL + hd * HSZ + ch * 8;
            cp16(kb + 0 * ARR + so, g_qkvh + gk);
            cp16(kb + 1 * ARR + so, g_qkvl + gk);
            cp16(kb + 2 * ARR + so, g_qkvh + gv);
            cp16(kb + 3 * ARR + so, g_qkvl + gv);
        }
        cp_commit();
    };

    issueKV(0);
    asm volatile("cp.async.wait_group 0;" ::: "memory");
    __syncthreads();

    uint32_t qh[4][4], ql[4][4];
#pragma unroll
    for (int ks = 0; ks < 4; ks++) {
        const uint32_t off =
            (uint32_t)((wid * 16 + (lane & 15)) * RS + ks * 32 + (lane >> 4) * 16);
        ldsm_x4(qh[ks], sb + QH_OFF + off);
        ldsm_x4(ql[ks], sb + QL_OFF + off);
    }

    float o[8][4];
#pragma unroll
    for (int nt = 0; nt < 8; nt++)
#pragma unroll
        for (int i = 0; i < 4; i++) o[nt][i] = 0.f;
    float m0 = -1e30f, m1 = -1e30f, l0 = 0.f, l1 = 0.f;

    const int ntiles = 2 * (bx + 1);
    for (int t = 0; t < ntiles; t++) {
        if (t + 1 < ntiles) {
            issueKV(t + 1);
            asm volatile("cp.async.wait_group 1;" ::: "memory");
        } else {
            asm volatile("cp.async.wait_group 0;" ::: "memory");
        }
        __syncthreads();
        const uint32_t kb = sb + KV_OFF + (uint32_t)((t & 1) * KV_STG);

        // ---- S = Q K^T (3-term), K frags via x4 pairs ----
        float s[8][4];
#pragma unroll
        for (int nt = 0; nt < 8; nt++)
#pragma unroll
            for (int i = 0; i < 4; i++) s[nt][i] = 0.f;
#pragma unroll
        for (int ks = 0; ks < 4; ks++) {
#pragma unroll
            for (int np = 0; np < 4; np++) {
                uint32_t b4h[4], b4l[4];
                const uint32_t offb = (uint32_t)((np * 16 + (lane & 15)) * RS +
                                                 ks * 32 + (lane >> 4) * 16);
                ldsm_x4(b4h, kb + 0 * ARR + offb);
                ldsm_x4(b4l, kb + 1 * ARR + offb);
                uint32_t bh0[2] = {b4h[0], b4h[2]}, bh1[2] = {b4h[1], b4h[3]};
                uint32_t bl0[2] = {b4l[0], b4l[2]}, bl1[2] = {b4l[1], b4l[3]};
                mma16816(s[2 * np], qh[ks], bh0);
                mma16816(s[2 * np], qh[ks], bl0);
                mma16816(s[2 * np], ql[ks], bh0);
                mma16816(s[2 * np + 1], qh[ks], bh1);
                mma16816(s[2 * np + 1], qh[ks], bl1);
                mma16816(s[2 * np + 1], ql[ks], bh1);
            }
        }

        // ---- scale + causal mask ----
        const int j0 = t * 64;
#pragma unroll
        for (int nt = 0; nt < 8; nt++)
#pragma unroll
            for (int i = 0; i < 4; i++) s[nt][i] *= scale;
        if (j0 + 63 > rbase) {
            const int r0 = rbase + (lane >> 2), r1 = r0 + 8;
#pragma unroll
            for (int nt = 0; nt < 8; nt++) {
                const int c0 = j0 + nt * 8 + (lane & 3) * 2;
                if (c0 > r0) s[nt][0] = -1e30f;
                if (c0 + 1 > r0) s[nt][1] = -1e30f;
                if (c0 > r1) s[nt][2] = -1e30f;
                if (c0 + 1 > r1) s[nt][3] = -1e30f;
            }
        }

        // ---- online softmax ----
        float rm0 = -1e30f, rm1 = -1e30f;
#pragma unroll
        for (int nt = 0; nt < 8; nt++) {
            rm0 = fmaxf(rm0, fmaxf(s[nt][0], s[nt][1]));
            rm1 = fmaxf(rm1, fmaxf(s[nt][2], s[nt][3]));
        }
        rm0 = fmaxf(rm0, __shfl_xor_sync(0xffffffffu, rm0, 1));
        rm0 = fmaxf(rm0, __shfl_xor_sync(0xffffffffu, rm0, 2));
        rm1 = fmaxf(rm1, __shfl_xor_sync(0xffffffffu, rm1, 1));
        rm1 = fmaxf(rm1, __shfl_xor_sync(0xffffffffu, rm1, 2));
        const float mn0 = fmaxf(m0, rm0), mn1 = fmaxf(m1, rm1);
        const float a0 = fexp(m0 - mn0), a1 = fexp(m1 - mn1);
        m0 = mn0;
        m1 = mn1;
        float ls0 = 0.f, ls1 = 0.f;
#pragma unroll
        for (int nt = 0; nt < 8; nt++) {
            s[nt][0] = fexp(s[nt][0] - m0);
            s[nt][1] = fexp(s[nt][1] - m0);
            s[nt][2] = fexp(s[nt][2] - m1);
            s[nt][3] = fexp(s[nt][3] - m1);
            ls0 += s[nt][0] + s[nt][1];
            ls1 += s[nt][2] + s[nt][3];
        }
        l0 = l0 * a0 + ls0;
        l1 = l1 * a1 + ls1;
#pragma unroll
        for (int nt = 0; nt < 8; nt++) {
            o[nt][0] *= a0;
            o[nt][1] *= a0;
            o[nt][2] *= a1;
            o[nt][3] *= a1;
        }

        // ---- O += P V (3-term; V frags via x4.trans pairs) ----
#pragma unroll
        for (int kk = 0; kk < 4; kk++) {
            uint32_t pah[4], pal[4];
            {
                const float* sA = s[2 * kk];
                const float* sB = s[2 * kk + 1];
                float hA0 = __bfloat162float(__float2bfloat16(sA[0]));
                float hA1 = __bfloat162float(__float2bfloat16(sA[1]));
                float hA2 = __bfloat162float(__float2bfloat16(sA[2]));
                float hA3 = __bfloat162float(__float2bfloat16(sA[3]));
                float hB0 = __bfloat162float(__float2bfloat16(sB[0]));
                float hB1 = __bfloat162float(__float2bfloat16(sB[1]));
                float hB2 = __bfloat162float(__float2bfloat16(sB[2]));
                float hB3 = __bfloat162float(__float2bfloat16(sB[3]));
                pah[0] = pack_bf16(hA0, hA1);
                pah[1] = pack_bf16(hA2, hA3);
                pah[2] = pack_bf16(hB0, hB1);
                pah[3] = pack_bf16(hB2, hB3);
                pal[0] = pack_bf16(sA[0] - hA0, sA[1] - hA1);
                pal[1] = pack_bf16(sA[2] - hA2, sA[3] - hA3);
                pal[2] = pack_bf16(sB[0] - hB0, sB[1] - hB1);
                pal[3] = pack_bf16(sB[2] - hB2, sB[3] - hB3);
            }
#pragma unroll
            for (int np = 0; np < 4; np++) {
                uint32_t v4h[4], v4l[4];
                const uint32_t offv = (uint32_t)((kk * 16 + (lane & 15)) * RS +
                                                 np * 32 + (lane >> 4) * 16);
                ldsm_x4t(v4h, kb + 2 * ARR + offv);
                ldsm_x4t(v4l, kb + 3 * ARR + offv);
                uint32_t vh0[2] = {v4h[0], v4h[1]}, vh1[2] = {v4h[2], v4h[3]};
                uint32_t vl0[2] = {v4l[0], v4l[1]}, vl1[2] = {v4l[2], v4l[3]};
                mma16816(o[2 * np], pah, vh0);
                mma16816(o[2 * np], pal, vh0);
                mma16816(o[2 * np], pah, vl0);
                mma16816(o[2 * np + 1], pah, vh1);
                mma16816(o[2 * np + 1], pal, vh1);
                mma16816(o[2 * np + 1], pah, vl1);
            }
        }
        __syncthreads();
    }

    // ---- finalize ----
    l0 += __shfl_xor_sync(0xffffffffu, l0, 1);
    l0 += __shfl_xor_sync(0xffffffffu, l0, 2);
    l1 += __shfl_xor_sync(0xffffffffu, l1, 1);
    l1 += __shfl_xor_sync(0xffffffffu, l1, 2);
    const float i0 = 1.f / l0, i1 = 1.f / l1;
    const int r0 = rbase + (lane >> 2);
#pragma unroll
    for (int nt = 0; nt < 8; nt++) {
        const int col = hd * HSZ + nt * 8 + (lane & 3) * 2;
        const float x0 = o[nt][0] * i0, x1 = o[nt][1] * i0;
        const float x2 = o[nt][2] * i1, x3 = o[nt][3] * i1;
        const bf16 h0 = __float2bfloat16(x0), h1 = __float2bfloat16(x1);
        const bf16 h2 = __float2bfloat16(x2), h3 = __float2bfloat16(x3);
        const size_t o0 = (size_t)r0 * DMODEL + col;
        const size_t o1 = (size_t)(r0 + 8) * DMODEL + col;
        *(__nv_bfloat162*)&g_oh[o0] = __nv_bfloat162(h0, h1);
        *(__nv_bfloat162*)&g_oh[o1] = __nv_bfloat162(h2, h3);
        *(__nv_bfloat162*)&g_ol[o0] = __nv_bfloat162(
            __float2bfloat16(x0 - __bfloat162float(h0)),
            __float2bfloat16(x1 - __bfloat162float(h1)));
        *(__nv_bfloat162*)&g_ol[o1] = __nv_bfloat162(
            __float2bfloat16(x2 - __bfloat162float(h2)),
            __float2bfloat16(x3 - __bfloat162float(h3)));
    }
}

// ---------------------------------------------------------------------------
extern "C" void kernel_launch(void* const* d_in, const int* in_sizes, int n_in,
                              void* d_out, int out_size) {
    const float* hs     = (const float*)d_in[0];
    const float* W_attn = (const float*)d_in[1];
    const float* b_attn = (const float*)d_in[2];
    const float* W_proj = (const float*)d_in[3];
    const float* b_proj = (const float*)d_in[4];
    float* out = (float*)d_out;

    bf16 *ah, *al, *wth, *wtl, *pth, *ptl, *qkvh, *qkvl, *oh, *ol;
    cudaGetSymbolAddress((void**)&ah, g_ah);
    cudaGetSymbolAddress((void**)&al, g_al);
    cudaGetSymbolAddress((void**)&wth, g_wth);
    cudaGetSymbolAddress((void**)&wtl, g_wtl);
    cudaGetSymbolAddress((void**)&pth, g_pth);
    cudaGetSymbolAddress((void**)&ptl, g_ptl);
    cudaGetSymbolAddress((void**)&qkvh, g_qkvh);
    cudaGetSymbolAddress((void**)&qkvl, g_qkvl);
    cudaGetSymbolAddress((void**)&oh, g_oh);
    cudaGetSymbolAddress((void**)&ol, g_ol);

    constexpr int GEMM_SMEM = 2 * 4 * 128 * 80;                  // 81920
    constexpr int ATTN_SMEM = 2 * 128 * 144 + 2 * 4 * 64 * 144;  // 110592
    cudaFuncSetAttribute(gemm_hmma<N3, DMODEL, true>,
                         cudaFuncAttributeMaxDynamicSharedMemorySize, GEMM_SMEM);
    cudaFuncSetAttribute(gemm_hmma<DMODEL, DMODEL, false>,
                         cudaFuncAttributeMaxDynamicSharedMemorySize, GEMM_SMEM);
    cudaFuncSetAttribute(attn_flash,
                         cudaFuncAttributeMaxDynamicSharedMemorySize, ATTN_SMEM);

    split_kernel<<<(S_LEN * DMODEL / 4) / 256, 256>>>(hs, ah, al);
    transpose_split<<<dim3(N3 / 32, DMODEL / 32), dim3(32, 8)>>>(W_attn, wth, wtl,
                                                                 DMODEL, N3);
    transpose_split<<<dim3(DMODEL / 32, DMODEL / 32), dim3(32, 8)>>>(W_proj, pth, ptl,
                                                                     DMODEL, DMODEL);
    gemm_hmma<N3, DMODEL, true><<<dim3(N3 / 128, S_LEN / 128), 256, GEMM_SMEM>>>(
        ah, al, wth, wtl, b_attn, nullptr, qkvh, qkvl);
    attn_flash<<<dim3(S_LEN / 128, NHEAD), 256, ATTN_SMEM>>>();
    gemm_hmma<DMODEL, DMODEL, false><<<dim3(DMODEL / 128, S_LEN / 128), 256, GEMM_SMEM>>>(
        oh, ol, pth, ptl, b_proj, out, nullptr, nullptr);
}

// round 13
// speedup vs baseline: 1.0975x; 1.0975x over previous
#include <cuda_runtime.h>
#include <cuda_bf16.h>
#include <cstdint>

#define S_LEN 2048
#define DMODEL 1024
#define NHEAD 16
#define HSZ 64
#define N3 (3 * DMODEL)

typedef __nv_bfloat16 bf16;

// ---------------- scratch (__device__ globals; no allocations) -------------
__device__ bf16 g_ah[S_LEN * DMODEL];        // hidden hi
__device__ bf16 g_al[S_LEN * DMODEL];        // hidden lo
__device__ bf16 g_wth[N3 * DMODEL];          // W_attn^T hi [3072,1024]
__device__ bf16 g_wtl[N3 * DMODEL];          // W_attn^T lo
__device__ bf16 g_pth[DMODEL * DMODEL];      // W_proj^T hi
__device__ bf16 g_ptl[DMODEL * DMODEL];      // W_proj^T lo
__device__ bf16 g_qkvh[S_LEN * N3];          // QKV hi (GEMM epilogue split)
__device__ bf16 g_qkvl[S_LEN * N3];          // QKV lo
__device__ bf16 g_oh[S_LEN * DMODEL];        // attn out hi
__device__ bf16 g_ol[S_LEN * DMODEL];        // attn out lo

// ---------------- PTX helpers (compute_103-safe, no 'a' features) ----------
__device__ __forceinline__ uint32_t smem_u32(const void* p) {
    uint32_t a;
    asm("{ .reg .u64 t; cvta.to.shared.u64 t, %1; cvt.u32.u64 %0, t; }"
        : "=r"(a) : "l"(p));
    return a;
}
__device__ __forceinline__ void cp16(uint32_t dst, const void* src) {
    asm volatile("cp.async.cg.shared.global [%0], [%1], 16;"
                 :: "r"(dst), "l"(src) : "memory");
}
__device__ __forceinline__ void cp_commit() {
    asm volatile("cp.async.commit_group;" ::: "memory");
}
__device__ __forceinline__ void ldsm_x4(uint32_t* r, uint32_t a) {
    asm volatile("ldmatrix.sync.aligned.m8n8.x4.shared.b16 {%0,%1,%2,%3}, [%4];"
                 : "=r"(r[0]), "=r"(r[1]), "=r"(r[2]), "=r"(r[3]) : "r"(a));
}
__device__ __forceinline__ void ldsm_x4t(uint32_t* r, uint32_t a) {
    asm volatile("ldmatrix.sync.aligned.m8n8.x4.trans.shared.b16 {%0,%1,%2,%3}, [%4];"
                 : "=r"(r[0]), "=r"(r[1]), "=r"(r[2]), "=r"(r[3]) : "r"(a));
}
__device__ __forceinline__ void mma16816(float* c, const uint32_t* a,
                                         const uint32_t* b) {
    asm volatile(
        "mma.sync.aligned.m16n8k16.row.col.f32.bf16.bf16.f32 "
        "{%0,%1,%2,%3}, {%4,%5,%6,%7}, {%8,%9}, {%0,%1,%2,%3};"
        : "+f"(c[0]), "+f"(c[1]), "+f"(c[2]), "+f"(c[3])
        : "r"(a[0]), "r"(a[1]), "r"(a[2]), "r"(a[3]), "r"(b[0]), "r"(b[1]));
}
// fma-pipe exp(x); rel err ~2e-6
__device__ __forceinline__ float fexp(float x) {
    float y = fmaxf(x * 1.4426950408889634f, -126.f);
    float z = y + 12582912.f;
    int i = __float_as_int(z) - 0x4B400000;
    float f = y - (z - 12582912.f);
    float p = 1.3333558146e-3f;
    p = fmaf(p, f, 9.6181291794e-3f);
    p = fmaf(p, f, 5.5504108665e-2f);
    p = fmaf(p, f, 2.4022650696e-1f);
    p = fmaf(p, f, 6.9314718056e-1f);
    p = fmaf(p, f, 1.0f);
    return __int_as_float(__float_as_int(p) + (i << 23));
}
__device__ __forceinline__ uint32_t pack_bf16(float x, float y) {
    __nv_bfloat162 t = __floats2bfloat162_rn(x, y);
    return *(uint32_t*)&t;
}

// ---------------------------------------------------------------------------
__global__ void split_kernel(const float* __restrict__ x,
                             bf16* __restrict__ hi, bf16* __restrict__ lo) {
    const int i = blockIdx.x * blockDim.x + threadIdx.x;
    float4 v = ((const float4*)x)[i];
    bf16 h0 = __float2bfloat16(v.x), h1 = __float2bfloat16(v.y);
    bf16 h2 = __float2bfloat16(v.z), h3 = __float2bfloat16(v.w);
    union { __nv_bfloat162 b[2]; uint2 u; } H, L;
    H.b[0] = __nv_bfloat162(h0, h1);
    H.b[1] = __nv_bfloat162(h2, h3);
    L.b[0] = __nv_bfloat162(__float2bfloat16(v.x - __bfloat162float(h0)),
                            __float2bfloat16(v.y - __bfloat162float(h1)));
    L.b[1] = __nv_bfloat162(__float2bfloat16(v.z - __bfloat162float(h2)),
                            __float2bfloat16(v.w - __bfloat162float(h3)));
    ((uint2*)hi)[i] = H.u;
    ((uint2*)lo)[i] = L.u;
}

__global__ void transpose_split(const float* __restrict__ W,
                                bf16* __restrict__ Th, bf16* __restrict__ Tl,
                                int K, int N) {
    __shared__ float tile[32][33];
    const int n0 = blockIdx.x * 32, k0 = blockIdx.y * 32;
    const int tx = threadIdx.x, ty = threadIdx.y;
#pragma unroll
    for (int i = 0; i < 4; i++)
        tile[ty + 8 * i][tx] = W[(size_t)(k0 + ty + 8 * i) * N + n0 + tx];
    __syncthreads();
#pragma unroll
    for (int i = 0; i < 4; i++) {
        const float x = tile[tx][ty + 8 * i];
        const bf16 h = __float2bfloat16(x);
        const size_t o = (size_t)(n0 + ty + 8 * i) * K + k0 + tx;
        Th[o] = h;
        Tl[o] = __float2bfloat16(x - __bfloat162float(h));
    }
}

// ---------------------------------------------------------------------------
// HMMA GEMM: C = Ah*Bh^T + Ah*Bl^T + Al*Bh^T + bias
// CTA 128x128, BK=32, 8 warps (2x4), warp tile 64x32, cp.async 2-stage.
// 1 CTA/SM (full register budget); TERM-MAJOR MMA order: same-accumulator
// reuse distance 16 MMAs instead of 1 (breaks RAW chains on tensor pipe).
// ---------------------------------------------------------------------------
template <int NDIM, int KDIM, bool SPLIT>
__global__ __launch_bounds__(256, 1)
void gemm_hmma(const bf16* __restrict__ Ah_, const bf16* __restrict__ Al_,
               const bf16* __restrict__ Bh_, const bf16* __restrict__ Bl_,
               const float* __restrict__ bias, float* __restrict__ C,
               bf16* __restrict__ Ch, bf16* __restrict__ Cl) {
    extern __shared__ __align__(128) char smem[];
    constexpr int TILE = 128 * 80;
    constexpr int STAGE = 4 * TILE;
    const int tid = threadIdx.x, lane = tid & 31, wid = tid >> 5;
    const int warp_m = wid & 1, warp_n = wid >> 1;
    const int bx = blockIdx.x, by = blockIdx.y;
    const uint32_t sb = smem_u32(smem);

    const bf16* gsrc[4] = {Ah_ + (size_t)(by * 128) * KDIM,
                           Al_ + (size_t)(by * 128) * KDIM,
                           Bh_ + (size_t)(bx * 128) * KDIM,
                           Bl_ + (size_t)(bx * 128) * KDIM};

    auto issue = [&](int t) {
        const uint32_t stb = sb + (uint32_t)((t & 1) * STAGE);
        const int k0 = t * 32;
#pragma unroll
        for (int tl = 0; tl < 4; tl++) {
#pragma unroll
            for (int i = 0; i < 2; i++) {
                const int c = tid + i * 256;
                const int row = c >> 2, cc = c & 3;
                cp16(stb + (uint32_t)(tl * TILE + row * 80 + cc * 16),
                     gsrc[tl] + (size_t)row * KDIM + k0 + cc * 8);
            }
        }
        cp_commit();
    };

    float c[4][4][4];
#pragma unroll
    for (int m = 0; m < 4; m++)
#pragma unroll
        for (int n = 0; n < 4; n++)
#pragma unroll
            for (int k = 0; k < 4; k++) c[m][n][k] = 0.f;

    issue(0);
    constexpr int NT = KDIM / 32;
    for (int t = 0; t < NT; t++) {
        if (t + 1 < NT) {
            issue(t + 1);
            asm volatile("cp.async.wait_group 1;" ::: "memory");
        } else {
            asm volatile("cp.async.wait_group 0;" ::: "memory");
        }
        __syncthreads();
        const uint32_t base = sb + (uint32_t)((t & 1) * STAGE);
#pragma unroll
        for (int ks = 0; ks < 2; ks++) {
            uint32_t ah[4][4], al[4][4], bh4[2][4], bl4[2][4];
#pragma unroll
            for (int mt = 0; mt < 4; mt++) {
                const int row = warp_m * 64 + mt * 16 + (lane & 15);
                const uint32_t off =
                    (uint32_t)(row * 80 + ks * 32 + (lane >> 4) * 16);
                ldsm_x4(ah[mt], base + 0 * TILE + off);
                ldsm_x4(al[mt], base + 1 * TILE + off);
            }
#pragma unroll
            for (int np = 0; np < 2; np++) {
                const int rowb = warp_n * 32 + np * 16 + (lane & 15);
                const uint32_t offb =
                    (uint32_t)(rowb * 80 + ks * 32 + (lane >> 4) * 16);
                ldsm_x4(bh4[np], base + 2 * TILE + offb);
                ldsm_x4(bl4[np], base + 3 * TILE + offb);
            }
            // unpack B frags once
            uint32_t bhf[4][2], blf[4][2];
#pragma unroll
            for (int nt = 0; nt < 4; nt++) {
                const int np = nt >> 1, od = nt & 1;
                bhf[nt][0] = bh4[np][od];
                bhf[nt][1] = bh4[np][od + 2];
                blf[nt][0] = bl4[np][od];
                blf[nt][1] = bl4[np][od + 2];
            }
            // term-major: 16 independent accumulators per pass
#pragma unroll
            for (int mt = 0; mt < 4; mt++)
#pragma unroll
                for (int nt = 0; nt < 4; nt++)
                    mma16816(c[mt][nt], ah[mt], bhf[nt]);
#pragma unroll
            for (int mt = 0; mt < 4; mt++)
#pragma unroll
                for (int nt = 0; nt < 4; nt++)
                    mma16816(c[mt][nt], ah[mt], blf[nt]);
#pragma unroll
            for (int mt = 0; mt < 4; mt++)
#pragma unroll
                for (int nt = 0; nt < 4; nt++)
                    mma16816(c[mt][nt], al[mt], bhf[nt]);
        }
        __syncthreads();
    }

#pragma unroll
    for (int mt = 0; mt < 4; mt++) {
        const int row0 = by * 128 + warp_m * 64 + mt * 16 + (lane >> 2);
#pragma unroll
        for (int nt = 0; nt < 4; nt++) {
            const int col = bx * 128 + warp_n * 32 + nt * 8 + (lane & 3) * 2;
            const float b0 = bias[col], b1 = bias[col + 1];
            const float v00 = c[mt][nt][0] + b0, v01 = c[mt][nt][1] + b1;
            const float v10 = c[mt][nt][2] + b0, v11 = c[mt][nt][3] + b1;
            if (SPLIT) {
                const bf16 h00 = __float2bfloat16(v00), h01 = __float2bfloat16(v01);
                const bf16 h10 = __float2bfloat16(v10), h11 = __float2bfloat16(v11);
                const size_t o0 = (size_t)row0 * NDIM + col;
                const size_t o1 = (size_t)(row0 + 8) * NDIM + col;
                *(__nv_bfloat162*)&Ch[o0] = __nv_bfloat162(h00, h01);
                *(__nv_bfloat162*)&Ch[o1] = __nv_bfloat162(h10, h11);
                *(__nv_bfloat162*)&Cl[o0] = __nv_bfloat162(
                    __float2bfloat16(v00 - __bfloat162float(h00)),
                    __float2bfloat16(v01 - __bfloat162float(h01)));
                *(__nv_bfloat162*)&Cl[o1] = __nv_bfloat162(
                    __float2bfloat16(v10 - __bfloat162float(h10)),
                    __float2bfloat16(v11 - __bfloat162float(h11)));
            } else {
                *(float2*)&C[(size_t)row0 * NDIM + col] = make_float2(v00, v01);
                *(float2*)&C[(size_t)(row0 + 8) * NDIM + col] = make_float2(v10, v11);
            }
        }
    }
}

// ---------------------------------------------------------------------------
// FlashAttention-2 causal, HMMA 3-term bf16. 1 head x 128 rows per CTA,
// 8 warps x m16, 64-key tiles, 1 CTA/SM, term-major MMA ordering.
// ---------------------------------------------------------------------------
__global__ __launch_bounds__(256, 1)
void attn_flash() {
    extern __shared__ __align__(128) char smem[];
    constexpr int RS = 144;
    constexpr int QH_OFF = 0, QL_OFF = 128 * RS;
    constexpr int KV_OFF = 2 * 128 * RS;
    constexpr int ARR = 64 * RS;
    constexpr int KV_STG = 4 * ARR;

    const int tid = threadIdx.x, lane = tid & 31, wid = tid >> 5;
    const int hd = blockIdx.y;
    const int bx = gridDim.x - 1 - blockIdx.x;   // heavy first
    const uint32_t sb = smem_u32(smem);
    const int rbase = bx * 128 + wid * 16;
    const float scale = rsqrtf((float)S_LEN);    // ref scales by sqrt(S)

    {
        const size_t qg = (size_t)(bx * 128) * N3 + hd * HSZ;
#pragma unroll
        for (int i = 0; i < 4; i++) {
            const int idx = tid + i * 256;
            const int row = idx >> 3, ch = idx & 7;
            const size_t g = qg + (size_t)row * N3 + ch * 8;
            cp16(sb + QH_OFF + (uint32_t)(row * RS + ch * 16), g_qkvh + g);
            cp16(sb + QL_OFF + (uint32_t)(row * RS + ch * 16), g_qkvl + g);
        }
    }

    auto issueKV = [&](int t) {
        const int stg = t & 1;
        const int j0 = t * 64;
        const uint32_t kb = sb + KV_OFF + (uint32_t)(stg * KV_STG);
#pragma unroll
        for (int i = 0; i < 2; i++) {
            const int idx = tid + i * 256;
            const int row = idx >> 3, ch = idx & 7;
            const uint32_t so = (uint32_t)(row * RS + ch * 16);
            const size_t gk = (size_t)(j0 + row) * N3 + DMODEL + hd * HSZ + ch * 8;
            const size_t gv = (size_t)(j0 + row) * N3 + 2 * DMODEL + hd * HSZ + ch * 8;
            cp16(kb + 0 * ARR + so, g_qkvh + gk);
            cp16(kb + 1 * ARR + so, g_qkvl + gk);
            cp16(kb + 2 * ARR + so, g_qkvh + gv);
            cp16(kb + 3 * ARR + so, g_qkvl + gv);
        }
        cp_commit();
    };

    issueKV(0);
    asm volatile("cp.async.wait_group 0;" ::: "memory");
    __syncthreads();

    uint32_t qh[4][4], ql[4][4];
#pragma unroll
    for (int ks = 0; ks < 4; ks++) {
        const uint32_t off =
            (uint32_t)((wid * 16 + (lane & 15)) * RS + ks * 32 + (lane >> 4) * 16);
        ldsm_x4(qh[ks], sb + QH_OFF + off);
        ldsm_x4(ql[ks], sb + QL_OFF + off);
    }

    float o[8][4];
#pragma unroll
    for (int nt = 0; nt < 8; nt++)
#pragma unroll
        for (int i = 0; i < 4; i++) o[nt][i] = 0.f;
    float m0 = -1e30f, m1 = -1e30f, l0 = 0.f, l1 = 0.f;

    const int ntiles = 2 * (bx + 1);
    for (int t = 0; t < ntiles; t++) {
        if (t + 1 < ntiles) {
            issueKV(t + 1);
            asm volatile("cp.async.wait_group 1;" ::: "memory");
        } else {
            asm volatile("cp.async.wait_group 0;" ::: "memory");
        }
        __syncthreads();
        const uint32_t kb = sb + KV_OFF + (uint32_t)((t & 1) * KV_STG);

        // ---- S = Q K^T (3-term), frags hoisted, term-major ----
        float s[8][4];
#pragma unroll
        for (int nt = 0; nt < 8; nt++)
#pragma unroll
            for (int i = 0; i < 4; i++) s[nt][i] = 0.f;
#pragma unroll
        for (int ks = 0; ks < 4; ks++) {
            uint32_t b4h[4][4], b4l[4][4];
#pragma unroll
            for (int np = 0; np < 4; np++) {
                const uint32_t offb = (uint32_t)((np * 16 + (lane & 15)) * RS +
                                                 ks * 32 + (lane >> 4) * 16);
                ldsm_x4(b4h[np], kb + 0 * ARR + offb);
                ldsm_x4(b4l[np], kb + 1 * ARR + offb);
            }
#pragma unroll
            for (int np = 0; np < 4; np++)
#pragma unroll
                for (int od = 0; od < 2; od++) {
                    uint32_t b[2] = {b4h[np][od], b4h[np][od + 2]};
                    mma16816(s[2 * np + od], qh[ks], b);
                }
#pragma unroll
            for (int np = 0; np < 4; np++)
#pragma unroll
                for (int od = 0; od < 2; od++) {
                    uint32_t b[2] = {b4l[np][od], b4l[np][od + 2]};
                    mma16816(s[2 * np + od], qh[ks], b);
                }
#pragma unroll
            for (int np = 0; np < 4; np++)
#pragma unroll
                for (int od = 0; od < 2; od++) {
                    uint32_t b[2] = {b4h[np][od], b4h[np][od + 2]};
                    mma16816(s[2 * np + od], ql[ks], b);
                }
        }

        // ---- scale + causal mask ----
        const int j0 = t * 64;
#pragma unroll
        for (int nt = 0; nt < 8; nt++)
#pragma unroll
            for (int i = 0; i < 4; i++) s[nt][i] *= scale;
        if (j0 + 63 > rbase) {
            const int r0 = rbase + (lane >> 2), r1 = r0 + 8;
#pragma unroll
            for (int nt = 0; nt < 8; nt++) {
                const int c0 = j0 + nt * 8 + (lane & 3) * 2;
                if (c0 > r0) s[nt][0] = -1e30f;
                if (c0 + 1 > r0) s[nt][1] = -1e30f;
                if (c0 > r1) s[nt][2] = -1e30f;
                if (c0 + 1 > r1) s[nt][3] = -1e30f;
            }
        }

        // ---- online softmax ----
        float rm0 = -1e30f, rm1 = -1e30f;
#pragma unroll
        for (int nt = 0; nt < 8; nt++) {
            rm0 = fmaxf(rm0, fmaxf(s[nt][0], s[nt][1]));
            rm1 = fmaxf(rm1, fmaxf(s[nt][2], s[nt][3]));
        }
        rm0 = fmaxf(rm0, __shfl_xor_sync(0xffffffffu, rm0, 1));
        rm0 = fmaxf(rm0, __shfl_xor_sync(0xffffffffu, rm0, 2));
        rm1 = fmaxf(rm1, __shfl_xor_sync(0xffffffffu, rm1, 1));
        rm1 = fmaxf(rm1, __shfl_xor_sync(0xffffffffu, rm1, 2));
        const float mn0 = fmaxf(m0, rm0), mn1 = fmaxf(m1, rm1);
        const float a0 = fexp(m0 - mn0), a1 = fexp(m1 - mn1);
        m0 = mn0;
        m1 = mn1;
        float ls0 = 0.f, ls1 = 0.f;
#pragma unroll
        for (int nt = 0; nt < 8; nt++) {
            s[nt][0] = fexp(s[nt][0] - m0);
            s[nt][1] = fexp(s[nt][1] - m0);
            s[nt][2] = fexp(s[nt][2] - m1);
            s[nt][3] = fexp(s[nt][3] - m1);
            ls0 += s[nt][0] + s[nt][1];
            ls1 += s[nt][2] + s[nt][3];
        }
        l0 = l0 * a0 + ls0;
        l1 = l1 * a1 + ls1;
#pragma unroll
        for (int nt = 0; nt < 8; nt++) {
            o[nt][0] *= a0;
            o[nt][1] *= a0;
            o[nt][2] *= a1;
            o[nt][3] *= a1;
        }

        // ---- O += P V (3-term; frags hoisted, term-major) ----
#pragma unroll
        for (int kk = 0; kk < 4; kk++) {
            uint32_t pah[4], pal[4];
            {
                const float* sA = s[2 * kk];
                const float* sB = s[2 * kk + 1];
                float hA0 = __bfloat162float(__float2bfloat16(sA[0]));
                float hA1 = __bfloat162float(__float2bfloat16(sA[1]));
                float hA2 = __bfloat162float(__float2bfloat16(sA[2]));
                float hA3 = __bfloat162float(__float2bfloat16(sA[3]));
                float hB0 = __bfloat162float(__float2bfloat16(sB[0]));
                float hB1 = __bfloat162float(__float2bfloat16(sB[1]));
                float hB2 = __bfloat162float(__float2bfloat16(sB[2]));
                float hB3 = __bfloat162float(__float2bfloat16(sB[3]));
                pah[0] = pack_bf16(hA0, hA1);
                pah[1] = pack_bf16(hA2, hA3);
                pah[2] = pack_bf16(hB0, hB1);
                pah[3] = pack_bf16(hB2, hB3);
                pal[0] = pack_bf16(sA[0] - hA0, sA[1] - hA1);
                pal[1] = pack_bf16(sA[2] - hA2, sA[3] - hA3);
                pal[2] = pack_bf16(sB[0] - hB0, sB[1] - hB1);
                pal[3] = pack_bf16(sB[2] - hB2, sB[3] - hB3);
            }
            uint32_t v4h[4][4], v4l[4][4];
#pragma unroll
            for (int np = 0; np < 4; np++) {
                const uint32_t offv = (uint32_t)((kk * 16 + (lane & 15)) * RS +
                                                 np * 32 + (lane >> 4) * 16);
                ldsm_x4t(v4h[np], kb + 2 * ARR + offv);
                ldsm_x4t(v4l[np], kb + 3 * ARR + offv);
            }
#pragma unroll
            for (int np = 0; np < 4; np++)
#pragma unroll
                for (int od = 0; od < 2; od++) {
                    uint32_t v[2] = {v4h[np][2 * od], v4h[np][2 * od + 1]};
                    mma16816(o[2 * np + od], pah, v);
                }
#pragma unroll
            for (int np = 0; np < 4; np++)
#pragma unroll
                for (int od = 0; od < 2; od++) {
                    uint32_t v[2] = {v4h[np][2 * od], v4h[np][2 * od + 1]};
                    mma16816(o[2 * np + od], pal, v);
                }
#pragma unroll
            for (int np = 0; np < 4; np++)
#pragma unroll
                for (int od = 0; od < 2; od++) {
                    uint32_t v[2] = {v4l[np][2 * od], v4l[np][2 * od + 1]};
                    mma16816(o[2 * np + od], pah, v);
                }
        }
        __syncthreads();
    }

    // ---- finalize ----
    l0 += __shfl_xor_sync(0xffffffffu, l0, 1);
    l0 += __shfl_xor_sync(0xffffffffu, l0, 2);
    l1 += __shfl_xor_sync(0xffffffffu, l1, 1);
    l1 += __shfl_xor_sync(0xffffffffu, l1, 2);
    const float i0 = 1.f / l0, i1 = 1.f / l1;
    const int r0 = rbase + (lane >> 2);
#pragma unroll
    for (int nt = 0; nt < 8; nt++) {
        const int col = hd * HSZ + nt * 8 + (lane & 3) * 2;
        const float x0 = o[nt][0] * i0, x1 = o[nt][1] * i0;
        const float x2 = o[nt][2] * i1, x3 = o[nt][3] * i1;
        const bf16 h0 = __float2bfloat16(x0), h1 = __float2bfloat16(x1);
        const bf16 h2 = __float2bfloat16(x2), h3 = __float2bfloat16(x3);
        const size_t o0 = (size_t)r0 * DMODEL + col;
        const size_t o1 = (size_t)(r0 + 8) * DMODEL + col;
        *(__nv_bfloat162*)&g_oh[o0] = __nv_bfloat162(h0, h1);
        *(__nv_bfloat162*)&g_oh[o1] = __nv_bfloat162(h2, h3);
        *(__nv_bfloat162*)&g_ol[o0] = __nv_bfloat162(
            __float2bfloat16(x0 - __bfloat162float(h0)),
            __float2bfloat16(x1 - __bfloat162float(h1)));
        *(__nv_bfloat162*)&g_ol[o1] = __nv_bfloat162(
            __float2bfloat16(x2 - __bfloat162float(h2)),
            __float2bfloat16(x3 - __bfloat162float(h3)));
    }
}

// ---------------------------------------------------------------------------
extern "C" void kernel_launch(void* const* d_in, const int* in_sizes, int n_in,
                              void* d_out, int out_size) {
    const float* hs     = (const float*)d_in[0];
    const float* W_attn = (const float*)d_in[1];
    const float* b_attn = (const float*)d_in[2];
    const float* W_proj = (const float*)d_in[3];
    const float* b_proj = (const float*)d_in[4];
    float* out = (float*)d_out;

    bf16 *ah, *al, *wth, *wtl, *pth, *ptl, *qkvh, *qkvl, *oh, *ol;
    cudaGetSymbolAddress((void**)&ah, g_ah);
    cudaGetSymbolAddress((void**)&al, g_al);
    cudaGetSymbolAddress((void**)&wth, g_wth);
    cudaGetSymbolAddress((void**)&wtl, g_wtl);
    cudaGetSymbolAddress((void**)&pth, g_pth);
    cudaGetSymbolAddress((void**)&ptl, g_ptl);
    cudaGetSymbolAddress((void**)&qkvh, g_qkvh);
    cudaGetSymbolAddress((void**)&qkvl, g_qkvl);
    cudaGetSymbolAddress((void**)&oh, g_oh);
    cudaGetSymbolAddress((void**)&ol, g_ol);

    constexpr int GEMM_SMEM = 2 * 4 * 128 * 80;                  // 81920
    constexpr int ATTN_SMEM = 2 * 128 * 144 + 2 * 4 * 64 * 144;  // 110592
    cudaFuncSetAttribute(gemm_hmma<N3, DMODEL, true>,
                         cudaFuncAttributeMaxDynamicSharedMemorySize, GEMM_SMEM);
    cudaFuncSetAttribute(gemm_hmma<DMODEL, DMODEL, false>,
                         cudaFuncAttributeMaxDynamicSharedMemorySize, GEMM_SMEM);
    cudaFuncSetAttribute(attn_flash,
                         cudaFuncAttributeMaxDynamicSharedMemorySize, ATTN_SMEM);

    split_kernel<<<(S_LEN * DMODEL / 4) / 256, 256>>>(hs, ah, al);
    transpose_split<<<dim3(N3 / 32, DMODEL / 32), dim3(32, 8)>>>(W_attn, wth, wtl,
                                                                 DMODEL, N3);
    transpose_split<<<dim3(DMODEL / 32, DMODEL / 32), dim3(32, 8)>>>(W_proj, pth, ptl,
                                                                     DMODEL, DMODEL);
    gemm_hmma<N3, DMODEL, true><<<dim3(N3 / 128, S_LEN / 128), 256, GEMM_SMEM>>>(
        ah, al, wth, wtl, b_attn, nullptr, qkvh, qkvl);
    attn_flash<<<dim3(S_LEN / 128, NHEAD), 256, ATTN_SMEM>>>();
    gemm_hmma<DMODEL, DMODEL, false><<<dim3(DMODEL / 128, S_LEN / 128), 256, GEMM_SMEM>>>(
        oh, ol, pth, ptl, b_proj, out, nullptr, nullptr);
}

// round 14
// speedup vs baseline: 1.2085x; 1.1012x over previous
#include <cuda_runtime.h>
#include <cuda_bf16.h>
#include <cstdint>

#define S_LEN 2048
#define DMODEL 1024
#define NHEAD 16
#define HSZ 64
#define N3 (3 * DMODEL)

typedef __nv_bfloat16 bf16;

// ---------------- scratch (__device__ globals; no allocations) -------------
__device__ bf16 g_ah[S_LEN * DMODEL];        // hidden hi
__device__ bf16 g_al[S_LEN * DMODEL];        // hidden lo
__device__ bf16 g_wth[N3 * DMODEL];          // W_attn^T hi [3072,1024]
__device__ bf16 g_wtl[N3 * DMODEL];          // W_attn^T lo
__device__ bf16 g_pth[DMODEL * DMODEL];      // W_proj^T hi
__device__ bf16 g_ptl[DMODEL * DMODEL];      // W_proj^T lo
__device__ bf16 g_qkvh[S_LEN * N3];          // QKV hi (GEMM epilogue split)
__device__ bf16 g_qkvl[S_LEN * N3];          // QKV lo
__device__ bf16 g_oh[S_LEN * DMODEL];        // attn out hi
__device__ bf16 g_ol[S_LEN * DMODEL];        // attn out lo

// ---------------- PTX helpers (compute_103-safe, no 'a' features) ----------
__device__ __forceinline__ uint32_t smem_u32(const void* p) {
    uint32_t a;
    asm("{ .reg .u64 t; cvta.to.shared.u64 t, %1; cvt.u32.u64 %0, t; }"
        : "=r"(a) : "l"(p));
    return a;
}
__device__ __forceinline__ void cp16(uint32_t dst, const void* src) {
    asm volatile("cp.async.cg.shared.global [%0], [%1], 16;"
                 :: "r"(dst), "l"(src) : "memory");
}
__device__ __forceinline__ void cp_commit() {
    asm volatile("cp.async.commit_group;" ::: "memory");
}
__device__ __forceinline__ void ldsm_x4(uint32_t* r, uint32_t a) {
    asm volatile("ldmatrix.sync.aligned.m8n8.x4.shared.b16 {%0,%1,%2,%3}, [%4];"
                 : "=r"(r[0]), "=r"(r[1]), "=r"(r[2]), "=r"(r[3]) : "r"(a));
}
__device__ __forceinline__ void ldsm_x2(uint32_t* r, uint32_t a) {
    asm volatile("ldmatrix.sync.aligned.m8n8.x2.shared.b16 {%0,%1}, [%2];"
                 : "=r"(r[0]), "=r"(r[1]) : "r"(a));
}
__device__ __forceinline__ void ldsm_x2t(uint32_t* r, uint32_t a) {
    asm volatile("ldmatrix.sync.aligned.m8n8.x2.trans.shared.b16 {%0,%1}, [%2];"
                 : "=r"(r[0]), "=r"(r[1]) : "r"(a));
}
__device__ __forceinline__ void mma16816(float* c, const uint32_t* a,
                                         const uint32_t* b) {
    asm volatile(
        "mma.sync.aligned.m16n8k16.row.col.f32.bf16.bf16.f32 "
        "{%0,%1,%2,%3}, {%4,%5,%6,%7}, {%8,%9}, {%0,%1,%2,%3};"
        : "+f"(c[0]), "+f"(c[1]), "+f"(c[2]), "+f"(c[3])
        : "r"(a[0]), "r"(a[1]), "r"(a[2]), "r"(a[3]), "r"(b[0]), "r"(b[1]));
}
// fma-pipe exp(x); rel err ~2e-6
__device__ __forceinline__ float fexp(float x) {
    float y = fmaxf(x * 1.4426950408889634f, -126.f);
    float z = y + 12582912.f;
    int i = __float_as_int(z) - 0x4B400000;
    float f = y - (z - 12582912.f);
    float p = 1.3333558146e-3f;
    p = fmaf(p, f, 9.6181291794e-3f);
    p = fmaf(p, f, 5.5504108665e-2f);
    p = fmaf(p, f, 2.4022650696e-1f);
    p = fmaf(p, f, 6.9314718056e-1f);
    p = fmaf(p, f, 1.0f);
    return __int_as_float(__float_as_int(p) + (i << 23));
}
__device__ __forceinline__ uint32_t pack_bf16(float x, float y) {
    __nv_bfloat162 t = __floats2bfloat162_rn(x, y);
    return *(uint32_t*)&t;
}

// ---------------------------------------------------------------------------
__global__ void split_kernel(const float* __restrict__ x,
                             bf16* __restrict__ hi, bf16* __restrict__ lo) {
    const int i = blockIdx.x * blockDim.x + threadIdx.x;
    float4 v = ((const float4*)x)[i];
    bf16 h0 = __float2bfloat16(v.x), h1 = __float2bfloat16(v.y);
    bf16 h2 = __float2bfloat16(v.z), h3 = __float2bfloat16(v.w);
    union { __nv_bfloat162 b[2]; uint2 u; } H, L;
    H.b[0] = __nv_bfloat162(h0, h1);
    H.b[1] = __nv_bfloat162(h2, h3);
    L.b[0] = __nv_bfloat162(__float2bfloat16(v.x - __bfloat162float(h0)),
                            __float2bfloat16(v.y - __bfloat162float(h1)));
    L.b[1] = __nv_bfloat162(__float2bfloat16(v.z - __bfloat162float(h2)),
                            __float2bfloat16(v.w - __bfloat162float(h3)));
    ((uint2*)hi)[i] = H.u;
    ((uint2*)lo)[i] = L.u;
}

__global__ void transpose_split(const float* __restrict__ W,
                                bf16* __restrict__ Th, bf16* __restrict__ Tl,
                                int K, int N) {
    __shared__ float tile[32][33];
    const int n0 = blockIdx.x * 32, k0 = blockIdx.y * 32;
    const int tx = threadIdx.x, ty = threadIdx.y;
#pragma unroll
    for (int i = 0; i < 4; i++)
        tile[ty + 8 * i][tx] = W[(size_t)(k0 + ty + 8 * i) * N + n0 + tx];
    __syncthreads();
#pragma unroll
    for (int i = 0; i < 4; i++) {
        const float x = tile[tx][ty + 8 * i];
        const bf16 h = __float2bfloat16(x);
        const size_t o = (size_t)(n0 + ty + 8 * i) * K + k0 + tx;
        Th[o] = h;
        Tl[o] = __float2bfloat16(x - __bfloat162float(h));
    }
}

// ---------------------------------------------------------------------------
// HMMA GEMM: C = Ah*Bh^T + Ah*Bl^T + Al*Bh^T + bias
// CTA 128x64, BK=32, 4 warps (2x2), warp tile 64x32, cp.async 2-stage.
// 128-thread CTAs -> 3 independent CTAs/SM (sync-decoupled warps per SMSP).
// Inner loop identical to the proven round-5 schedule.
// ---------------------------------------------------------------------------
template <int NDIM, int KDIM, bool SPLIT>
__global__ __launch_bounds__(128, 3)
void gemm_hmma(const bf16* __restrict__ Ah_, const bf16* __restrict__ Al_,
               const bf16* __restrict__ Bh_, const bf16* __restrict__ Bl_,
               const float* __restrict__ bias, float* __restrict__ C,
               bf16* __restrict__ Ch, bf16* __restrict__ Cl) {
    extern __shared__ __align__(128) char smem[];
    constexpr int TILE_A = 128 * 80;          // 128 rows x (64B data + 16B pad)
    constexpr int TILE_B = 64 * 80;
    constexpr int OFF_AH = 0, OFF_AL = TILE_A, OFF_BH = 2 * TILE_A,
                  OFF_BL = 2 * TILE_A + TILE_B;
    constexpr int STAGE = 2 * TILE_A + 2 * TILE_B;   // 30720
    const int tid = threadIdx.x, lane = tid & 31, wid = tid >> 5;
    const int warp_m = wid & 1, warp_n = wid >> 1;   // 2x2
    const int bx = blockIdx.x, by = blockIdx.y;
    const uint32_t sb = smem_u32(smem);

    const bf16* Abh = Ah_ + (size_t)(by * 128) * KDIM;
    const bf16* Abl = Al_ + (size_t)(by * 128) * KDIM;
    const bf16* Bbh = Bh_ + (size_t)(bx * 64) * KDIM;
    const bf16* Bbl = Bl_ + (size_t)(bx * 64) * KDIM;

    auto issue = [&](int t) {
        const uint32_t stb = sb + (uint32_t)((t & 1) * STAGE);
        const int k0 = t * 32;
        // A hi/lo: 512 chunks of 16B each (128 rows x 4)
#pragma unroll
        for (int i = 0; i < 4; i++) {
            const int c = tid + i * 128;
            const int row = c >> 2, cc = c & 3;
            const size_t g = (size_t)row * KDIM + k0 + cc * 8;
            cp16(stb + OFF_AH + (uint32_t)(row * 80 + cc * 16), Abh + g);
            cp16(stb + OFF_AL + (uint32_t)(row * 80 + cc * 16), Abl + g);
        }
        // B hi/lo: 256 chunks each (64 rows x 4)
#pragma unroll
        for (int i = 0; i < 2; i++) {
            const int c = tid + i * 128;
            const int row = c >> 2, cc = c & 3;
            const size_t g = (size_t)row * KDIM + k0 + cc * 8;
            cp16(stb + OFF_BH + (uint32_t)(row * 80 + cc * 16), Bbh + g);
            cp16(stb + OFF_BL + (uint32_t)(row * 80 + cc * 16), Bbl + g);
        }
        cp_commit();
    };

    float c[4][4][4];
#pragma unroll
    for (int m = 0; m < 4; m++)
#pragma unroll
        for (int n = 0; n < 4; n++)
#pragma unroll
            for (int k = 0; k < 4; k++) c[m][n][k] = 0.f;

    issue(0);
    constexpr int NT = KDIM / 32;
    for (int t = 0; t < NT; t++) {
        if (t + 1 < NT) {
            issue(t + 1);
            asm volatile("cp.async.wait_group 1;" ::: "memory");
        } else {
            asm volatile("cp.async.wait_group 0;" ::: "memory");
        }
        __syncthreads();
        const uint32_t base = sb + (uint32_t)((t & 1) * STAGE);
#pragma unroll
        for (int ks = 0; ks < 2; ks++) {
            uint32_t ah[4][4], al[4][4], bh[4][2], bl[4][2];
#pragma unroll
            for (int mt = 0; mt < 4; mt++) {
                const int row = warp_m * 64 + mt * 16 + (lane & 15);
                const uint32_t off =
                    (uint32_t)(row * 80 + ks * 32 + (lane >> 4) * 16);
                ldsm_x4(ah[mt], base + OFF_AH + off);
                ldsm_x4(al[mt], base + OFF_AL + off);
            }
#pragma unroll
            for (int nt = 0; nt < 4; nt++) {
                const int rowb = warp_n * 32 + nt * 8 + (lane & 7);
                const uint32_t offb =
                    (uint32_t)(rowb * 80 + ks * 32 + ((lane >> 3) & 1) * 16);
                ldsm_x2(bh[nt], base + OFF_BH + offb);
                ldsm_x2(bl[nt], base + OFF_BL + offb);
            }
#pragma unroll
            for (int mt = 0; mt < 4; mt++)
#pragma unroll
                for (int nt = 0; nt < 4; nt++) {
                    mma16816(c[mt][nt], ah[mt], bh[nt]);
                    mma16816(c[mt][nt], ah[mt], bl[nt]);
                    mma16816(c[mt][nt], al[mt], bh[nt]);
                }
        }
        __syncthreads();
    }

#pragma unroll
    for (int mt = 0; mt < 4; mt++) {
        const int row0 = by * 128 + warp_m * 64 + mt * 16 + (lane >> 2);
#pragma unroll
        for (int nt = 0; nt < 4; nt++) {
            const int col = bx * 64 + warp_n * 32 + nt * 8 + (lane & 3) * 2;
            const float b0 = bias[col], b1 = bias[col + 1];
            const float v00 = c[mt][nt][0] + b0, v01 = c[mt][nt][1] + b1;
            const float v10 = c[mt][nt][2] + b0, v11 = c[mt][nt][3] + b1;
            if (SPLIT) {
                const bf16 h00 = __float2bfloat16(v00), h01 = __float2bfloat16(v01);
                const bf16 h10 = __float2bfloat16(v10), h11 = __float2bfloat16(v11);
                const size_t o0 = (size_t)row0 * NDIM + col;
                const size_t o1 = (size_t)(row0 + 8) * NDIM + col;
                *(__nv_bfloat162*)&Ch[o0] = __nv_bfloat162(h00, h01);
                *(__nv_bfloat162*)&Ch[o1] = __nv_bfloat162(h10, h11);
                *(__nv_bfloat162*)&Cl[o0] = __nv_bfloat162(
                    __float2bfloat16(v00 - __bfloat162float(h00)),
                    __float2bfloat16(v01 - __bfloat162float(h01)));
                *(__nv_bfloat162*)&Cl[o1] = __nv_bfloat162(
                    __float2bfloat16(v10 - __bfloat162float(h10)),
                    __float2bfloat16(v11 - __bfloat162float(h11)));
            } else {
                *(float2*)&C[(size_t)row0 * NDIM + col] = make_float2(v00, v01);
                *(float2*)&C[(size_t)(row0 + 8) * NDIM + col] = make_float2(v10, v11);
            }
        }
    }
}

// ---------------------------------------------------------------------------
// FlashAttention-2 causal, HMMA 3-term bf16 (exact round-5 proven version).
// 1 head x 128 rows per CTA, 8 warps x m16, 64-key tiles.
// ---------------------------------------------------------------------------
__global__ __launch_bounds__(256, 1)
void attn_flash() {
    extern __shared__ __align__(128) char smem[];
    constexpr int RS = 144;
    constexpr int QH_OFF = 0, QL_OFF = 128 * RS;
    constexpr int KV_OFF = 2 * 128 * RS;
    constexpr int ARR = 64 * RS;
    constexpr int KV_STG = 4 * ARR;

    const int tid = threadIdx.x, lane = tid & 31, wid = tid >> 5;
    const int hd = blockIdx.y;
    const int bx = gridDim.x - 1 - blockIdx.x;   // heavy first
    const uint32_t sb = smem_u32(smem);
    const int rbase = bx * 128 + wid * 16;
    const float scale = rsqrtf((float)S_LEN);    // ref scales by sqrt(S)

    {
        const size_t qg = (size_t)(bx * 128) * N3 + hd * HSZ;
#pragma unroll
        for (int i = 0; i < 4; i++) {
            const int idx = tid + i * 256;
            const int row = idx >> 3, ch = idx & 7;
            const size_t g = qg + (size_t)row * N3 + ch * 8;
            cp16(sb + QH_OFF + (uint32_t)(row * RS + ch * 16), g_qkvh + g);
            cp16(sb + QL_OFF + (uint32_t)(row * RS + ch * 16), g_qkvl + g);
        }
    }

    auto issueKV = [&](int t) {
        const int stg = t & 1;
        const int j0 = t * 64;
        const uint32_t kb = sb + KV_OFF + (uint32_t)(stg * KV_STG);
#pragma unroll
        for (int i = 0; i < 2; i++) {
            const int idx = tid + i * 256;
            const int row = idx >> 3, ch = idx & 7;
            const uint32_t so = (uint32_t)(row * RS + ch * 16);
            const size_t gk = (size_t)(j0 + row) * N3 + DMODEL + hd * HSZ + ch * 8;
            const size_t gv = (size_t)(j0 + row) * N3 + 2 * DMODEL + hd * HSZ + ch * 8;
            cp16(kb + 0 * ARR + so, g_qkvh + gk);
            cp16(kb + 1 * ARR + so, g_qkvl + gk);
            cp16(kb + 2 * ARR + so, g_qkvh + gv);
            cp16(kb + 3 * ARR + so, g_qkvl + gv);
        }
        cp_commit();
    };

    issueKV(0);
    asm volatile("cp.async.wait_group 0;" ::: "memory");
    __syncthreads();

    uint32_t qh[4][4], ql[4][4];
#pragma unroll
    for (int ks = 0; ks < 4; ks++) {
        const uint32_t off =
            (uint32_t)((wid * 16 + (lane & 15)) * RS + ks * 32 + (lane >> 4) * 16);
        ldsm_x4(qh[ks], sb + QH_OFF + off);
        ldsm_x4(ql[ks], sb + QL_OFF + off);
    }

    float o[8][4];
#pragma unroll
    for (int nt = 0; nt < 8; nt++)
#pragma unroll
        for (int i = 0; i < 4; i++) o[nt][i] = 0.f;
    float m0 = -1e30f, m1 = -1e30f, l0 = 0.f, l1 = 0.f;

    const int ntiles = 2 * (bx + 1);
    for (int t = 0; t < ntiles; t++) {
        if (t + 1 < ntiles) {
            issueKV(t + 1);
            asm volatile("cp.async.wait_group 1;" ::: "memory");
        } else {
            asm volatile("cp.async.wait_group 0;" ::: "memory");
        }
        __syncthreads();
        const uint32_t kb = sb + KV_OFF + (uint32_t)((t & 1) * KV_STG);

        // ---- S = Q K^T (3-term) ----
        float s[8][4];
#pragma unroll
        for (int nt = 0; nt < 8; nt++)
#pragma unroll
            for (int i = 0; i < 4; i++) s[nt][i] = 0.f;
#pragma unroll
        for (int ks = 0; ks < 4; ks++) {
#pragma unroll
            for (int nt = 0; nt < 8; nt++) {
                uint32_t bh[2], bl[2];
                const uint32_t offb = (uint32_t)((nt * 8 + (lane & 7)) * RS +
                                                 ks * 32 + ((lane >> 3) & 1) * 16);
                ldsm_x2(bh, kb + 0 * ARR + offb);
                ldsm_x2(bl, kb + 1 * ARR + offb);
                mma16816(s[nt], qh[ks], bh);
                mma16816(s[nt], qh[ks], bl);
                mma16816(s[nt], ql[ks], bh);
            }
        }

        // ---- scale + causal mask ----
        const int j0 = t * 64;
#pragma unroll
        for (int nt = 0; nt < 8; nt++)
#pragma unroll
            for (int i = 0; i < 4; i++) s[nt][i] *= scale;
        if (j0 + 63 > rbase) {
            const int r0 = rbase + (lane >> 2), r1 = r0 + 8;
#pragma unroll
            for (int nt = 0; nt < 8; nt++) {
                const int c0 = j0 + nt * 8 + (lane & 3) * 2;
                if (c0 > r0) s[nt][0] = -1e30f;
                if (c0 + 1 > r0) s[nt][1] = -1e30f;
                if (c0 > r1) s[nt][2] = -1e30f;
                if (c0 + 1 > r1) s[nt][3] = -1e30f;
            }
        }

        // ---- online softmax ----
        float rm0 = -1e30f, rm1 = -1e30f;
#pragma unroll
        for (int nt = 0; nt < 8; nt++) {
            rm0 = fmaxf(rm0, fmaxf(s[nt][0], s[nt][1]));
            rm1 = fmaxf(rm1, fmaxf(s[nt][2], s[nt][3]));
        }
        rm0 = fmaxf(rm0, __shfl_xor_sync(0xffffffffu, rm0, 1));
        rm0 = fmaxf(rm0, __shfl_xor_sync(0xffffffffu, rm0, 2));
        rm1 = fmaxf(rm1, __shfl_xor_sync(0xffffffffu, rm1, 1));
        rm1 = fmaxf(rm1, __shfl_xor_sync(0xffffffffu, rm1, 2));
        const float mn0 = fmaxf(m0, rm0), mn1 = fmaxf(m1, rm1);
        const float a0 = fexp(m0 - mn0), a1 = fexp(m1 - mn1);
        m0 = mn0;
        m1 = mn1;
        float ls0 = 0.f, ls1 = 0.f;
#pragma unroll
        for (int nt = 0; nt < 8; nt++) {
            s[nt][0] = fexp(s[nt][0] - m0);
            s[nt][1] = fexp(s[nt][1] - m0);
            s[nt][2] = fexp(s[nt][2] - m1);
            s[nt][3] = fexp(s[nt][3] - m1);
            ls0 += s[nt][0] + s[nt][1];
            ls1 += s[nt][2] + s[nt][3];
        }
        l0 = l0 * a0 + ls0;
        l1 = l1 * a1 + ls1;
#pragma unroll
        for (int nt = 0; nt < 8; nt++) {
            o[nt][0] *= a0;
            o[nt][1] *= a0;
            o[nt][2] *= a1;
            o[nt][3] *= a1;
        }

        // ---- O += P V (3-term; score frags reused as A frags) ----
#pragma unroll
        for (int kk = 0; kk < 4; kk++) {
            uint32_t pah[4], pal[4];
            {
                const float* sA = s[2 * kk];
                const float* sB = s[2 * kk + 1];
                float hA0 = __bfloat162float(__float2bfloat16(sA[0]));
                float hA1 = __bfloat162float(__float2bfloat16(sA[1]));
                float hA2 = __bfloat162float(__float2bfloat16(sA[2]));
                float hA3 = __bfloat162float(__float2bfloat16(sA[3]));
                float hB0 = __bfloat162float(__float2bfloat16(sB[0]));
                float hB1 = __bfloat162float(__float2bfloat16(sB[1]));
                float hB2 = __bfloat162float(__float2bfloat16(sB[2]));
                float hB3 = __bfloat162float(__float2bfloat16(sB[3]));
                pah[0] = pack_bf16(hA0, hA1);
                pah[1] = pack_bf16(hA2, hA3);
                pah[2] = pack_bf16(hB0, hB1);
                pah[3] = pack_bf16(hB2, hB3);
                pal[0] = pack_bf16(sA[0] - hA0, sA[1] - hA1);
                pal[1] = pack_bf16(sA[2] - hA2, sA[3] - hA3);
                pal[2] = pack_bf16(sB[0] - hB0, sB[1] - hB1);
                pal[3] = pack_bf16(sB[2] - hB2, sB[3] - hB3);
            }
#pragma unroll
            for (int nt = 0; nt < 8; nt++) {
                uint32_t bvh[2], bvl[2];
                const uint32_t offv =
                    (uint32_t)((kk * 16 + (lane & 15)) * RS + nt * 16);
                ldsm_x2t(bvh, kb + 2 * ARR + offv);
                ldsm_x2t(bvl, kb + 3 * ARR + offv);
                mma16816(o[nt], pah, bvh);
                mma16816(o[nt], pal, bvh);
                mma16816(o[nt], pah, bvl);
            }
        }
        __syncthreads();
    }

    // ---- finalize ----
    l0 += __shfl_xor_sync(0xffffffffu, l0, 1);
    l0 += __shfl_xor_sync(0xffffffffu, l0, 2);
    l1 += __shfl_xor_sync(0xffffffffu, l1, 1);
    l1 += __shfl_xor_sync(0xffffffffu, l1, 2);
    const float i0 = 1.f / l0, i1 = 1.f / l1;
    const int r0 = rbase + (lane >> 2);
#pragma unroll
    for (int nt = 0; nt < 8; nt++) {
        const int col = hd * HSZ + nt * 8 + (lane & 3) * 2;
        const float x0 = o[nt][0] * i0, x1 = o[nt][1] * i0;
        const float x2 = o[nt][2] * i1, x3 = o[nt][3] * i1;
        const bf16 h0 = __float2bfloat16(x0), h1 = __float2bfloat16(x1);
        const bf16 h2 = __float2bfloat16(x2), h3 = __float2bfloat16(x3);
        const size_t o0 = (size_t)r0 * DMODEL + col;
        const size_t o1 = (size_t)(r0 + 8) * DMODEL + col;
        *(__nv_bfloat162*)&g_oh[o0] = __nv_bfloat162(h0, h1);
        *(__nv_bfloat162*)&g_oh[o1] = __nv_bfloat162(h2, h3);
        *(__nv_bfloat162*)&g_ol[o0] = __nv_bfloat162(
            __float2bfloat16(x0 - __bfloat162float(h0)),
            __float2bfloat16(x1 - __bfloat162float(h1)));
        *(__nv_bfloat162*)&g_ol[o1] = __nv_bfloat162(
            __float2bfloat16(x2 - __bfloat162float(h2)),
            __float2bfloat16(x3 - __bfloat162float(h3)));
    }
}

// ---------------------------------------------------------------------------
extern "C" void kernel_launch(void* const* d_in, const int* in_sizes, int n_in,
                              void* d_out, int out_size) {
    const float* hs     = (const float*)d_in[0];
    const float* W_attn = (const float*)d_in[1];
    const float* b_attn = (const float*)d_in[2];
    const float* W_proj = (const float*)d_in[3];
    const float* b_proj = (const float*)d_in[4];
    float* out = (float*)d_out;

    bf16 *ah, *al, *wth, *wtl, *pth, *ptl, *qkvh, *qkvl, *oh, *ol;
    cudaGetSymbolAddress((void**)&ah, g_ah);
    cudaGetSymbolAddress((void**)&al, g_al);
    cudaGetSymbolAddress((void**)&wth, g_wth);
    cudaGetSymbolAddress((void**)&wtl, g_wtl);
    cudaGetSymbolAddress((void**)&pth, g_pth);
    cudaGetSymbolAddress((void**)&ptl, g_ptl);
    cudaGetSymbolAddress((void**)&qkvh, g_qkvh);
    cudaGetSymbolAddress((void**)&qkvl, g_qkvl);
    cudaGetSymbolAddress((void**)&oh, g_oh);
    cudaGetSymbolAddress((void**)&ol, g_ol);

    constexpr int GEMM_SMEM = 2 * (2 * 128 * 80 + 2 * 64 * 80);  // 61440
    constexpr int ATTN_SMEM = 2 * 128 * 144 + 2 * 4 * 64 * 144;  // 110592
    cudaFuncSetAttribute(gemm_hmma<N3, DMODEL, true>,
                         cudaFuncAttributeMaxDynamicSharedMemorySize, GEMM_SMEM);
    cudaFuncSetAttribute(gemm_hmma<DMODEL, DMODEL, false>,
                         cudaFuncAttributeMaxDynamicSharedMemorySize, GEMM_SMEM);
    cudaFuncSetAttribute(attn_flash,
                         cudaFuncAttributeMaxDynamicSharedMemorySize, ATTN_SMEM);

    split_kernel<<<(S_LEN * DMODEL / 4) / 256, 256>>>(hs, ah, al);
    transpose_split<<<dim3(N3 / 32, DMODEL / 32), dim3(32, 8)>>>(W_attn, wth, wtl,
                                                                 DMODEL, N3);
    transpose_split<<<dim3(DMODEL / 32, DMODEL / 32), dim3(32, 8)>>>(W_proj, pth, ptl,
                                                                     DMODEL, DMODEL);
    gemm_hmma<N3, DMODEL, true><<<dim3(N3 / 64, S_LEN / 128), 128, GEMM_SMEM>>>(
        ah, al, wth, wtl, b_attn, nullptr, qkvh, qkvl);
    attn_flash<<<dim3(S_LEN / 128, NHEAD), 256, ATTN_SMEM>>>();
    gemm_hmma<DMODEL, DMODEL, false><<<dim3(DMODEL / 64, S_LEN / 128), 128, GEMM_SMEM>>>(
        oh, ol, pth, ptl, b_proj, out, nullptr, nullptr);
}

// round 17
// speedup vs baseline: 1.2379x; 1.0243x over previous
#include <cuda_runtime.h>
#include <cuda_bf16.h>
#include <cstdint>

#define S_LEN 2048
#define DMODEL 1024
#define NHEAD 16
#define HSZ 64
#define N3 (3 * DMODEL)

typedef __nv_bfloat16 bf16;

// ---------------- scratch (__device__ globals; no allocations) -------------
__device__ bf16 g_ah[S_LEN * DMODEL];        // hidden hi
__device__ bf16 g_al[S_LEN * DMODEL];        // hidden lo
__device__ bf16 g_wth[N3 * DMODEL];          // W_attn^T hi [3072,1024]
__device__ bf16 g_wtl[N3 * DMODEL];          // W_attn^T lo
__device__ bf16 g_pth[DMODEL * DMODEL];      // W_proj^T hi
__device__ bf16 g_ptl[DMODEL * DMODEL];      // W_proj^T lo
__device__ bf16 g_qkvh[S_LEN * N3];          // QKV hi (GEMM epilogue split)
__device__ bf16 g_qkvl[S_LEN * N3];          // QKV lo
__device__ bf16 g_oh[S_LEN * DMODEL];        // attn out hi
__device__ bf16 g_ol[S_LEN * DMODEL];        // attn out lo

// ---------------- PTX helpers (compute_103-safe, no 'a' features) ----------
__device__ __forceinline__ uint32_t smem_u32(const void* p) {
    uint32_t a;
    asm("{ .reg .u64 t; cvta.to.shared.u64 t, %1; cvt.u32.u64 %0, t; }"
        : "=r"(a) : "l"(p));
    return a;
}
__device__ __forceinline__ void cp16(uint32_t dst, const void* src) {
    asm volatile("cp.async.cg.shared.global [%0], [%1], 16;"
                 :: "r"(dst), "l"(src) : "memory");
}
__device__ __forceinline__ void cp_commit() {
    asm volatile("cp.async.commit_group;" ::: "memory");
}
__device__ __forceinline__ void ldsm_x4(uint32_t* r, uint32_t a) {
    asm volatile("ldmatrix.sync.aligned.m8n8.x4.shared.b16 {%0,%1,%2,%3}, [%4];"
                 : "=r"(r[0]), "=r"(r[1]), "=r"(r[2]), "=r"(r[3]) : "r"(a));
}
__device__ __forceinline__ void ldsm_x2(uint32_t* r, uint32_t a) {
    asm volatile("ldmatrix.sync.aligned.m8n8.x2.shared.b16 {%0,%1}, [%2];"
                 : "=r"(r[0]), "=r"(r[1]) : "r"(a));
}
__device__ __forceinline__ void ldsm_x2t(uint32_t* r, uint32_t a) {
    asm volatile("ldmatrix.sync.aligned.m8n8.x2.trans.shared.b16 {%0,%1}, [%2];"
                 : "=r"(r[0]), "=r"(r[1]) : "r"(a));
}
__device__ __forceinline__ void mma16816(float* c, const uint32_t* a,
                                         const uint32_t* b) {
    asm volatile(
        "mma.sync.aligned.m16n8k16.row.col.f32.bf16.bf16.f32 "
        "{%0,%1,%2,%3}, {%4,%5,%6,%7}, {%8,%9}, {%0,%1,%2,%3};"
        : "+f"(c[0]), "+f"(c[1]), "+f"(c[2]), "+f"(c[3])
        : "r"(a[0]), "r"(a[1]), "r"(a[2]), "r"(a[3]), "r"(b[0]), "r"(b[1]));
}
// fma-pipe exp(x); rel err ~2e-6
__device__ __forceinline__ float fexp(float x) {
    float y = fmaxf(x * 1.4426950408889634f, -126.f);
    float z = y + 12582912.f;
    int i = __float_as_int(z) - 0x4B400000;
    float f = y - (z - 12582912.f);
    float p = 1.3333558146e-3f;
    p = fmaf(p, f, 9.6181291794e-3f);
    p = fmaf(p, f, 5.5504108665e-2f);
    p = fmaf(p, f, 2.4022650696e-1f);
    p = fmaf(p, f, 6.9314718056e-1f);
    p = fmaf(p, f, 1.0f);
    return __int_as_float(__float_as_int(p) + (i << 23));
}
__device__ __forceinline__ uint32_t pack_bf16(float x, float y) {
    __nv_bfloat162 t = __floats2bfloat162_rn(x, y);
    return *(uint32_t*)&t;
}

// ---------------------------------------------------------------------------
__global__ void split_kernel(const float* __restrict__ x,
                             bf16* __restrict__ hi, bf16* __restrict__ lo) {
    const int i = blockIdx.x * blockDim.x + threadIdx.x;
    float4 v = ((const float4*)x)[i];
    bf16 h0 = __float2bfloat16(v.x), h1 = __float2bfloat16(v.y);
    bf16 h2 = __float2bfloat16(v.z), h3 = __float2bfloat16(v.w);
    union { __nv_bfloat162 b[2]; uint2 u; } H, L;
    H.b[0] = __nv_bfloat162(h0, h1);
    H.b[1] = __nv_bfloat162(h2, h3);
    L.b[0] = __nv_bfloat162(__float2bfloat16(v.x - __bfloat162float(h0)),
                            __float2bfloat16(v.y - __bfloat162float(h1)));
    L.b[1] = __nv_bfloat162(__float2bfloat16(v.z - __bfloat162float(h2)),
                            __float2bfloat16(v.w - __bfloat162float(h3)));
    ((uint2*)hi)[i] = H.u;
    ((uint2*)lo)[i] = L.u;
}

__global__ void transpose_split(const float* __restrict__ W,
                                bf16* __restrict__ Th, bf16* __restrict__ Tl,
                                int K, int N) {
    __shared__ float tile[32][33];
    const int n0 = blockIdx.x * 32, k0 = blockIdx.y * 32;
    const int tx = threadIdx.x, ty = threadIdx.y;
#pragma unroll
    for (int i = 0; i < 4; i++)
        tile[ty + 8 * i][tx] = W[(size_t)(k0 + ty + 8 * i) * N + n0 + tx];
    __syncthreads();
#pragma unroll
    for (int i = 0; i < 4; i++) {
        const float x = tile[tx][ty + 8 * i];
        const bf16 h = __float2bfloat16(x);
        const size_t o = (size_t)(n0 + ty + 8 * i) * K + k0 + tx;
        Th[o] = h;
        Tl[o] = __float2bfloat16(x - __bfloat162float(h));
    }
}

// ---------------------------------------------------------------------------
// HMMA GEMM: C = Ah*Bh^T + Ah*Bl^T + Al*Bh^T + bias
// CTA 64x64, BK=32, 2 warps (64 thr), warp tile 64x32, cp.async 2-stage.
// 64-thread CTAs -> 5 independent CTAs/SM (max sync-decoupling per SMSP).
// Inner warp schedule identical to the proven round-5/14 version.
// ---------------------------------------------------------------------------
template <int NDIM, int KDIM, bool SPLIT>
__global__ __launch_bounds__(64, 5)
void gemm_hmma(const bf16* __restrict__ Ah_, const bf16* __restrict__ Al_,
               const bf16* __restrict__ Bh_, const bf16* __restrict__ Bl_,
               const float* __restrict__ bias, float* __restrict__ C,
               bf16* __restrict__ Ch, bf16* __restrict__ Cl) {
    extern __shared__ __align__(128) char smem[];
    constexpr int TILE = 64 * 80;             // 64 rows x (64B data + 16B pad)
    constexpr int OFF_AH = 0, OFF_AL = TILE, OFF_BH = 2 * TILE,
                  OFF_BL = 3 * TILE;
    constexpr int STAGE = 4 * TILE;           // 20480
    const int tid = threadIdx.x, lane = tid & 31, wid = tid >> 5;
    const int warp_n = wid;                   // 2 warps split N (32 cols each)
    const int bx = blockIdx.x, by = blockIdx.y;
    const uint32_t sb = smem_u32(smem);

    const bf16* Abh = Ah_ + (size_t)(by * 64) * KDIM;
    const bf16* Abl = Al_ + (size_t)(by * 64) * KDIM;
    const bf16* Bbh = Bh_ + (size_t)(bx * 64) * KDIM;
    const bf16* Bbl = Bl_ + (size_t)(bx * 64) * KDIM;

    auto issue = [&](int t) {
        const uint32_t stb = sb + (uint32_t)((t & 1) * STAGE);
        const int k0 = t * 32;
        // each array: 64 rows x 4 chunks of 16B = 256 chunks; 4 per thread
#pragma unroll
        for (int i = 0; i < 4; i++) {
            const int c = tid + i * 64;
            const int row = c >> 2, cc = c & 3;
            const uint32_t so = (uint32_t)(row * 80 + cc * 16);
            const size_t g = (size_t)row * KDIM + k0 + cc * 8;
            cp16(stb + OFF_AH + so, Abh + g);
            cp16(stb + OFF_AL + so, Abl + g);
            cp16(stb + OFF_BH + so, Bbh + g);
            cp16(stb + OFF_BL + so, Bbl + g);
        }
        cp_commit();
    };

    float c[4][4][4];
#pragma unroll
    for (int m = 0; m < 4; m++)
#pragma unroll
        for (int n = 0; n < 4; n++)
#pragma unroll
            for (int k = 0; k < 4; k++) c[m][n][k] = 0.f;

    issue(0);
    constexpr int NT = KDIM / 32;
    for (int t = 0; t < NT; t++) {
        if (t + 1 < NT) {
            issue(t + 1);
            asm volatile("cp.async.wait_group 1;" ::: "memory");
        } else {
            asm volatile("cp.async.wait_group 0;" ::: "memory");
        }
        __syncthreads();
        const uint32_t base = sb + (uint32_t)((t & 1) * STAGE);
#pragma unroll
        for (int ks = 0; ks < 2; ks++) {
            uint32_t ah[4][4], al[4][4], bh[4][2], bl[4][2];
#pragma unroll
            for (int mt = 0; mt < 4; mt++) {
                const int row = mt * 16 + (lane & 15);
                const uint32_t off =
                    (uint32_t)(row * 80 + ks * 32 + (lane >> 4) * 16);
                ldsm_x4(ah[mt], base + OFF_AH + off);
                ldsm_x4(al[mt], base + OFF_AL + off);
            }
#pragma unroll
            for (int nt = 0; nt < 4; nt++) {
                const int rowb = warp_n * 32 + nt * 8 + (lane & 7);
                const uint32_t offb =
                    (uint32_t)(rowb * 80 + ks * 32 + ((lane >> 3) & 1) * 16);
                ldsm_x2(bh[nt], base + OFF_BH + offb);
                ldsm_x2(bl[nt], base + OFF_BL + offb);
            }
#pragma unroll
            for (int mt = 0; mt < 4; mt++)
#pragma unroll
                for (int nt = 0; nt < 4; nt++) {
                    mma16816(c[mt][nt], ah[mt], bh[nt]);
                    mma16816(c[mt][nt], ah[mt], bl[nt]);
                    mma16816(c[mt][nt], al[mt], bh[nt]);
                }
        }
        __syncthreads();
    }

#pragma unroll
    for (int mt = 0; mt < 4; mt++) {
        const int row0 = by * 64 + mt * 16 + (lane >> 2);
#pragma unroll
        for (int nt = 0; nt < 4; nt++) {
            const int col = bx * 64 + warp_n * 32 + nt * 8 + (lane & 3) * 2;
            const float b0 = bias[col], b1 = bias[col + 1];
            const float v00 = c[mt][nt][0] + b0, v01 = c[mt][nt][1] + b1;
            const float v10 = c[mt][nt][2] + b0, v11 = c[mt][nt][3] + b1;
            if (SPLIT) {
                const bf16 h00 = __float2bfloat16(v00), h01 = __float2bfloat16(v01);
                const bf16 h10 = __float2bfloat16(v10), h11 = __float2bfloat16(v11);
                const size_t o0 = (size_t)row0 * NDIM + col;
                const size_t o1 = (size_t)(row0 + 8) * NDIM + col;
                *(__nv_bfloat162*)&Ch[o0] = __nv_bfloat162(h00, h01);
                *(__nv_bfloat162*)&Ch[o1] = __nv_bfloat162(h10, h11);
                *(__nv_bfloat162*)&Cl[o0] = __nv_bfloat162(
                    __float2bfloat16(v00 - __bfloat162float(h00)),
                    __float2bfloat16(v01 - __bfloat162float(h01)));
                *(__nv_bfloat162*)&Cl[o1] = __nv_bfloat162(
                    __float2bfloat16(v10 - __bfloat162float(h10)),
                    __float2bfloat16(v11 - __bfloat162float(h11)));
            } else {
                *(float2*)&C[(size_t)row0 * NDIM + col] = make_float2(v00, v01);
                *(float2*)&C[(size_t)(row0 + 8) * NDIM + col] = make_float2(v10, v11);
            }
        }
    }
}

// ---------------------------------------------------------------------------
// FlashAttention-2 causal, HMMA 3-term bf16 (round-14 proven version).
// 1 head x 128 rows per CTA, 8 warps x m16, 64-key tiles.
// ---------------------------------------------------------------------------
__global__ __launch_bounds__(256, 1)
void attn_flash() {
    extern __shared__ __align__(128) char smem[];
    constexpr int RS = 144;
    constexpr int QH_OFF = 0, QL_OFF = 128 * RS;
    constexpr int KV_OFF = 2 * 128 * RS;
    constexpr int ARR = 64 * RS;
    constexpr int KV_STG = 4 * ARR;

    const int tid = threadIdx.x, lane = tid & 31, wid = tid >> 5;
    const int hd = blockIdx.y;
    const int bx = gridDim.x - 1 - blockIdx.x;   // heavy first
    const uint32_t sb = smem_u32(smem);
    const int rbase = bx * 128 + wid * 16;
    const float scale = rsqrtf((float)S_LEN);    // ref scales by sqrt(S)

    {
        const size_t qg = (size_t)(bx * 128) * N3 + hd * HSZ;
#pragma unroll
        for (int i = 0; i < 4; i++) {
            const int idx = tid + i * 256;
            const int row = idx >> 3, ch = idx & 7;
            const size_t g = qg + (size_t)row * N3 + ch * 8;
            cp16(sb + QH_OFF + (uint32_t)(row * RS + ch * 16), g_qkvh + g);
            cp16(sb + QL_OFF + (uint32_t)(row * RS + ch * 16), g_qkvl + g);
        }
    }

    auto issueKV = [&](int t) {
        const int stg = t & 1;
        const int j0 = t * 64;
        const uint32_t kb = sb + KV_OFF + (uint32_t)(stg * KV_STG);
#pragma unroll
        for (int i = 0; i < 2; i++) {
            const int idx = tid + i * 256;
            const int row = idx >> 3, ch = idx & 7;
            const uint32_t so = (uint32_t)(row * RS + ch * 16);
            const size_t gk = (size_t)(j0 + row) * N3 + DMODEL + hd * HSZ + ch * 8;
            const size_t gv = (size_t)(j0 + row) * N3 + 2 * DMODEL + hd * HSZ + ch * 8;
            cp16(kb + 0 * ARR + so, g_qkvh + gk);
            cp16(kb + 1 * ARR + so, g_qkvl + gk);
            cp16(kb + 2 * ARR + so, g_qkvh + gv);
            cp16(kb + 3 * ARR + so, g_qkvl + gv);
        }
        cp_commit();
    };

    issueKV(0);
    asm volatile("cp.async.wait_group 0;" ::: "memory");
    __syncthreads();

    uint32_t qh[4][4], ql[4][4];
#pragma unroll
    for (int ks = 0; ks < 4; ks++) {
        const uint32_t off =
            (uint32_t)((wid * 16 + (lane & 15)) * RS + ks * 32 + (lane >> 4) * 16);
        ldsm_x4(qh[ks], sb + QH_OFF + off);
        ldsm_x4(ql[ks], sb + QL_OFF + off);
    }

    float o[8][4];
#pragma unroll
    for (int nt = 0; nt < 8; nt++)
#pragma unroll
        for (int i = 0; i < 4; i++) o[nt][i] = 0.f;
    float m0 = -1e30f, m1 = -1e30f, l0 = 0.f, l1 = 0.f;

    const int ntiles = 2 * (bx + 1);
    for (int t = 0; t < ntiles; t++) {
        if (t + 1 < ntiles) {
            issueKV(t + 1);
            asm volatile("cp.async.wait_group 1;" ::: "memory");
        } else {
            asm volatile("cp.async.wait_group 0;" ::: "memory");
        }
        __syncthreads();
        const uint32_t kb = sb + KV_OFF + (uint32_t)((t & 1) * KV_STG);

        // ---- S = Q K^T (3-term) ----
        float s[8][4];
#pragma unroll
        for (int nt = 0; nt < 8; nt++)
#pragma unroll
            for (int i = 0; i < 4; i++) s[nt][i] = 0.f;
#pragma unroll
        for (int ks = 0; ks < 4; ks++) {
#pragma unroll
            for (int nt = 0; nt < 8; nt++) {
                uint32_t bh[2], bl[2];
                const uint32_t offb = (uint32_t)((nt * 8 + (lane & 7)) * RS +
                                                 ks * 32 + ((lane >> 3) & 1) * 16);
                ldsm_x2(bh, kb + 0 * ARR + offb);
                ldsm_x2(bl, kb + 1 * ARR + offb);
                mma16816(s[nt], qh[ks], bh);
                mma16816(s[nt], qh[ks], bl);
                mma16816(s[nt], ql[ks], bh);
            }
        }

        // ---- scale + causal mask ----
        const int j0 = t * 64;
#pragma unroll
        for (int nt = 0; nt < 8; nt++)
#pragma unroll
            for (int i = 0; i < 4; i++) s[nt][i] *= scale;
        if (j0 + 63 > rbase) {
            const int r0 = rbase + (lane >> 2), r1 = r0 + 8;
#pragma unroll
            for (int nt = 0; nt < 8; nt++) {
                const int c0 = j0 + nt * 8 + (lane & 3) * 2;
                if (c0 > r0) s[nt][0] = -1e30f;
                if (c0 + 1 > r0) s[nt][1] = -1e30f;
                if (c0 > r1) s[nt][2] = -1e30f;
                if (c0 + 1 > r1) s[nt][3] = -1e30f;
            }
        }

        // ---- online softmax ----
        float rm0 = -1e30f, rm1 = -1e30f;
#pragma unroll
        for (int nt = 0; nt < 8; nt++) {
            rm0 = fmaxf(rm0, fmaxf(s[nt][0], s[nt][1]));
            rm1 = fmaxf(rm1, fmaxf(s[nt][2], s[nt][3]));
        }
        rm0 = fmaxf(rm0, __shfl_xor_sync(0xffffffffu, rm0, 1));
        rm0 = fmaxf(rm0, __shfl_xor_sync(0xffffffffu, rm0, 2));
        rm1 = fmaxf(rm1, __shfl_xor_sync(0xffffffffu, rm1, 1));
        rm1 = fmaxf(rm1, __shfl_xor_sync(0xffffffffu, rm1, 2));
        const float mn0 = fmaxf(m0, rm0), mn1 = fmaxf(m1, rm1);
        const float a0 = fexp(m0 - mn0), a1 = fexp(m1 - mn1);
        m0 = mn0;
        m1 = mn1;
        float ls0 = 0.f, ls1 = 0.f;
#pragma unroll
        for (int nt = 0; nt < 8; nt++) {
            s[nt][0] = fexp(s[nt][0] - m0);
            s[nt][1] = fexp(s[nt][1] - m0);
            s[nt][2] = fexp(s[nt][2] - m1);
            s[nt][3] = fexp(s[nt][3] - m1);
            ls0 += s[nt][0] + s[nt][1];
            ls1 += s[nt][2] + s[nt][3];
        }
        l0 = l0 * a0 + ls0;
        l1 = l1 * a1 + ls1;
#pragma unroll
        for (int nt = 0; nt < 8; nt++) {
            o[nt][0] *= a0;
            o[nt][1] *= a0;
            o[nt][2] *= a1;
            o[nt][3] *= a1;
        }

        // ---- O += P V (3-term; score frags reused as A frags) ----
#pragma unroll
        for (int kk = 0; kk < 4; kk++) {
            uint32_t pah[4], pal[4];
            {
                const float* sA = s[2 * kk];
                const float* sB = s[2 * kk + 1];
                float hA0 = __bfloat162float(__float2bfloat16(sA[0]));
                float hA1 = __bfloat162float(__float2bfloat16(sA[1]));
                float hA2 = __bfloat162float(__float2bfloat16(sA[2]));
                float hA3 = __bfloat162float(__float2bfloat16(sA[3]));
                float hB0 = __bfloat162float(__float2bfloat16(sB[0]));
                float hB1 = __bfloat162float(__float2bfloat16(sB[1]));
                float hB2 = __bfloat162float(__float2bfloat16(sB[2]));
                float hB3 = __bfloat162float(__float2bfloat16(sB[3]));
                pah[0] = pack_bf16(hA0, hA1);
                pah[1] = pack_bf16(hA2, hA3);
                pah[2] = pack_bf16(hB0, hB1);
                pah[3] = pack_bf16(hB2, hB3);
                pal[0] = pack_bf16(sA[0] - hA0, sA[1] - hA1);
                pal[1] = pack_bf16(sA[2] - hA2, sA[3] - hA3);
                pal[2] = pack_bf16(sB[0] - hB0, sB[1] - hB1);
                pal[3] = pack_bf16(sB[2] - hB2, sB[3] - hB3);
            }
#pragma unroll
            for (int nt = 0; nt < 8; nt++) {
                uint32_t bvh[2], bvl[2];
                const uint32_t offv =
                    (uint32_t)((kk * 16 + (lane & 15)) * RS + nt * 16);
                ldsm_x2t(bvh, kb + 2 * ARR + offv);
                ldsm_x2t(bvl, kb + 3 * ARR + offv);
                mma16816(o[nt], pah, bvh);
                mma16816(o[nt], pal, bvh);
                mma16816(o[nt], pah, bvl);
            }
        }
        __syncthreads();
    }

    // ---- finalize ----
    l0 += __shfl_xor_sync(0xffffffffu, l0, 1);
    l0 += __shfl_xor_sync(0xffffffffu, l0, 2);
    l1 += __shfl_xor_sync(0xffffffffu, l1, 1);
    l1 += __shfl_xor_sync(0xffffffffu, l1, 2);
    const float i0 = 1.f / l0, i1 = 1.f / l1;
    const int r0 = rbase + (lane >> 2);
#pragma unroll
    for (int nt = 0; nt < 8; nt++) {
        const int col = hd * HSZ + nt * 8 + (lane & 3) * 2;
        const float x0 = o[nt][0] * i0, x1 = o[nt][1] * i0;
        const float x2 = o[nt][2] * i1, x3 = o[nt][3] * i1;
        const bf16 h0 = __float2bfloat16(x0), h1 = __float2bfloat16(x1);
        const bf16 h2 = __float2bfloat16(x2), h3 = __float2bfloat16(x3);
        const size_t o0 = (size_t)r0 * DMODEL + col;
        const size_t o1 = (size_t)(r0 + 8) * DMODEL + col;
        *(__nv_bfloat162*)&g_oh[o0] = __nv_bfloat162(h0, h1);
        *(__nv_bfloat162*)&g_oh[o1] = __nv_bfloat162(h2, h3);
        *(__nv_bfloat162*)&g_ol[o0] = __nv_bfloat162(
            __float2bfloat16(x0 - __bfloat162float(h0)),
            __float2bfloat16(x1 - __bfloat162float(h1)));
        *(__nv_bfloat162*)&g_ol[o1] = __nv_bfloat162(
            __float2bfloat16(x2 - __bfloat162float(h2)),
            __float2bfloat16(x3 - __bfloat162float(h3)));
    }
}

// ---------------------------------------------------------------------------
extern "C" void kernel_launch(void* const* d_in, const int* in_sizes, int n_in,
                              void* d_out, int out_size) {
    const float* hs     = (const float*)d_in[0];
    const float* W_attn = (const float*)d_in[1];
    const float* b_attn = (const float*)d_in[2];
    const float* W_proj = (const float*)d_in[3];
    const float* b_proj = (const float*)d_in[4];
    float* out = (float*)d_out;

    bf16 *ah, *al, *wth, *wtl, *pth, *ptl, *qkvh, *qkvl, *oh, *ol;
    cudaGetSymbolAddress((void**)&ah, g_ah);
    cudaGetSymbolAddress((void**)&al, g_al);
    cudaGetSymbolAddress((void**)&wth, g_wth);
    cudaGetSymbolAddress((void**)&wtl, g_wtl);
    cudaGetSymbolAddress((void**)&pth, g_pth);
    cudaGetSymbolAddress((void**)&ptl, g_ptl);
    cudaGetSymbolAddress((void**)&qkvh, g_qkvh);
    cudaGetSymbolAddress((void**)&qkvl, g_qkvl);
    cudaGetSymbolAddress((void**)&oh, g_oh);
    cudaGetSymbolAddress((void**)&ol, g_ol);

    constexpr int GEMM_SMEM = 2 * 4 * 64 * 80;                   // 40960
    constexpr int ATTN_SMEM = 2 * 128 * 144 + 2 * 4 * 64 * 144;  // 110592
    cudaFuncSetAttribute(gemm_hmma<N3, DMODEL, true>,
                         cudaFuncAttributeMaxDynamicSharedMemorySize, GEMM_SMEM);
    cudaFuncSetAttribute(gemm_hmma<DMODEL, DMODEL, false>,
                         cudaFuncAttributeMaxDynamicSharedMemorySize, GEMM_SMEM);
    cudaFuncSetAttribute(attn_flash,
                         cudaFuncAttributeMaxDynamicSharedMemorySize, ATTN_SMEM);

    split_kernel<<<(S_LEN * DMODEL / 4) / 256, 256>>>(hs, ah, al);
    transpose_split<<<dim3(N3 / 32, DMODEL / 32), dim3(32, 8)>>>(W_attn, wth, wtl,
                                                                 DMODEL, N3);
    transpose_split<<<dim3(DMODEL / 32, DMODEL / 32), dim3(32, 8)>>>(W_proj, pth, ptl,
                                                                     DMODEL, DMODEL);
    gemm_hmma<N3, DMODEL, true><<<dim3(N3 / 64, S_LEN / 64), 64, GEMM_SMEM>>>(
        ah, al, wth, wtl, b_attn, nullptr, qkvh, qkvl);
    attn_flash<<<dim3(S_LEN / 128, NHEAD), 256, ATTN_SMEM>>>();
    gemm_hmma<DMODEL, DMODEL, false><<<dim3(DMODEL / 64, S_LEN / 64), 64, GEMM_SMEM>>>(
        oh, ol, pth, ptl, b_proj, out, nullptr, nullptr);
}